// round 7
// baseline (speedup 1.0000x reference)
#include <cuda_runtime.h>
#include <cuda_bf16.h>
#include <math.h>
#include <stdint.h>

// Problem constants (B=1)
#define SEQ   2048
#define HID   4096
#define NHEAD 32
#define HDIM  128
#define QKV_N 12288            // 3*HID
#define INV_NORM 0.08838834764831845f   // 1/sqrt(128)

// Scratch buffers (device globals; runtime alloc forbidden)
static __device__ float g_qkv[(size_t)SEQ * QKV_N];          // [S, NH*3*HD]
static __device__ float g_ctx[(size_t)SEQ * HID];            // [S, NH*HD]
static __device__ __nv_bfloat16 g_Wqkv_hi[(size_t)QKV_N * HID];
static __device__ __nv_bfloat16 g_Wqkv_lo[(size_t)QKV_N * HID];
static __device__ __nv_bfloat16 g_Wd_hi[(size_t)HID * HID];
static __device__ __nv_bfloat16 g_Wd_lo[(size_t)HID * HID];
static __device__ __nv_bfloat16 g_A_hi[(size_t)SEQ * HID];
static __device__ __nv_bfloat16 g_A_lo[(size_t)SEQ * HID];

// ---------------------------------------------------------------------------
// helpers
// ---------------------------------------------------------------------------
__device__ __forceinline__ uint32_t smem_u32(const void* p) {
    uint32_t a;
    asm("{ .reg .u64 t; cvta.to.shared.u64 t, %1; cvt.u32.u64 %0, t; }" : "=r"(a) : "l"(p));
    return a;
}
__device__ __forceinline__ void ldsm4(uint32_t* r, uint32_t addr) {
    asm volatile("ldmatrix.sync.aligned.m8n8.x4.shared.b16 {%0,%1,%2,%3}, [%4];"
                 : "=r"(r[0]), "=r"(r[1]), "=r"(r[2]), "=r"(r[3]) : "r"(addr));
}
__device__ __forceinline__ void mma16816(float* c, const uint32_t* a, const uint32_t* b) {
    asm volatile(
        "mma.sync.aligned.m16n8k16.row.col.f32.bf16.bf16.f32 "
        "{%0,%1,%2,%3}, {%4,%5,%6,%7}, {%8,%9}, {%0,%1,%2,%3};"
        : "+f"(c[0]), "+f"(c[1]), "+f"(c[2]), "+f"(c[3])
        : "r"(a[0]), "r"(a[1]), "r"(a[2]), "r"(a[3]), "r"(b[0]), "r"(b[1]));
}
__device__ __forceinline__ void cp16(uint32_t dst, const void* src) {
    asm volatile("cp.async.cg.shared.global [%0], [%1], 16;" :: "r"(dst), "l"(src) : "memory");
}
__device__ __forceinline__ void cp_commit() {
    asm volatile("cp.async.commit_group;" ::: "memory");
}
template <int N>
__device__ __forceinline__ void cp_wait() {
    asm volatile("cp.async.wait_group %0;" :: "n"(N) : "memory");
}

// ---------------------------------------------------------------------------
// fp32 -> (hi, lo) bf16 split, elementwise (grid-stride, float4)
// ---------------------------------------------------------------------------
__global__ void split_kernel(const float* __restrict__ x, __nv_bfloat16* __restrict__ hi,
                             __nv_bfloat16* __restrict__ lo, int n)
{
    const int stride = gridDim.x * blockDim.x * 4;
    for (int i = (blockIdx.x * blockDim.x + threadIdx.x) * 4; i < n; i += stride) {
        const float4 v = *(const float4*)(x + i);
        __nv_bfloat162 h0 = __floats2bfloat162_rn(v.x, v.y);
        __nv_bfloat162 h1 = __floats2bfloat162_rn(v.z, v.w);
        __nv_bfloat162 l0 = __floats2bfloat162_rn(v.x - __bfloat162float(h0.x),
                                                  v.y - __bfloat162float(h0.y));
        __nv_bfloat162 l1 = __floats2bfloat162_rn(v.z - __bfloat162float(h1.x),
                                                  v.w - __bfloat162float(h1.y));
        *(uint2*)(hi + i) = make_uint2(*(uint32_t*)&h0, *(uint32_t*)&h1);
        *(uint2*)(lo + i) = make_uint2(*(uint32_t*)&l0, *(uint32_t*)&l1);
    }
}

// ---------------------------------------------------------------------------
// Split-bf16 HMMA TN GEMM, cp.async 3-stage pipeline.
// C[m,n] = sum_k A[m,k]*B[n,k] + bias[n] (+ add[m,n])
// A,B already split into hi/lo bf16 [rows][K].
// CTA tile 128x128, BK=32, 8 warps (2m x 4n), warp tile 64x32.
// smem rows padded to 40 bf16 (80B, 16B-aligned) -> conflict-free ldmatrix.
// ---------------------------------------------------------------------------
#define SSTRIDE 40
#define STAGES 3
#define BK 32
#define BUF_BYTES (128 * SSTRIDE * 2)        // 10240
#define STAGE_BYTES (4 * BUF_BYTES)          // 40960: Ah, Al, Bh, Bl
#define GSM_TOTAL (STAGES * STAGE_BYTES)     // 122880

__global__ __launch_bounds__(256, 1)
void gemm_hmma(const __nv_bfloat16* __restrict__ Ahg, const __nv_bfloat16* __restrict__ Alg,
               const __nv_bfloat16* __restrict__ Bhg, const __nv_bfloat16* __restrict__ Blg,
               const float* __restrict__ bias, const float* __restrict__ add,
               float* __restrict__ C, int M, int N, int K)
{
    extern __shared__ char smem[];
    const uint32_t sb = smem_u32(smem);

    const int tid  = threadIdx.x;
    const int wid  = tid >> 5;
    const int lane = tid & 31;
    const int bm = blockIdx.y * 128;
    const int bn = blockIdx.x * 128;

    const int warp_m = (wid & 1) * 64;
    const int warp_n = (wid >> 1) * 32;

    // loader mapping: thread -> row (0..127), 16-col half (0 or 16)
    const int lrow = tid >> 1;
    const int lcol = (tid & 1) * 16;
    const __nv_bfloat16* gAh = Ahg + (size_t)(bm + lrow) * K + lcol;
    const __nv_bfloat16* gAl = Alg + (size_t)(bm + lrow) * K + lcol;
    const __nv_bfloat16* gBh = Bhg + (size_t)(bn + lrow) * K + lcol;
    const __nv_bfloat16* gBl = Blg + (size_t)(bn + lrow) * K + lcol;
    const uint32_t sdst = (uint32_t)(lrow * SSTRIDE + lcol) * 2;

    // ldmatrix lane addressing (as validated in R5)
    const int a_r = warp_m + (lane & 15);
    const int a_c = (lane >> 4) * 8;
    const int b_r = warp_n + (lane >> 4) * 8 + (lane & 7);
    const int b_c = ((lane >> 3) & 1) * 8;

    float acc[4][4][4];
#pragma unroll
    for (int i = 0; i < 4; i++)
#pragma unroll
        for (int j = 0; j < 4; j++)
#pragma unroll
            for (int e = 0; e < 4; e++) acc[i][j][e] = 0.0f;

    const int NCH = K >> 5;

    // issue one stage's loads (8 x cp.async of 16B per thread)
    auto issue = [&](int ch) {
        const uint32_t base = sb + (uint32_t)(ch % STAGES) * STAGE_BYTES;
        const int ko = ch * BK;
        cp16(base + sdst,                     gAh + ko);
        cp16(base + sdst + 16,                gAh + ko + 8);
        cp16(base + BUF_BYTES + sdst,         gAl + ko);
        cp16(base + BUF_BYTES + sdst + 16,    gAl + ko + 8);
        cp16(base + 2 * BUF_BYTES + sdst,     gBh + ko);
        cp16(base + 2 * BUF_BYTES + sdst + 16, gBh + ko + 8);
        cp16(base + 3 * BUF_BYTES + sdst,     gBl + ko);
        cp16(base + 3 * BUF_BYTES + sdst + 16, gBl + ko + 8);
        cp_commit();
    };

    // prologue: STAGES-1 stages in flight
#pragma unroll
    for (int ch = 0; ch < STAGES - 1; ch++) issue(ch);

    for (int ch = 0; ch < NCH; ch++) {
        cp_wait<STAGES - 2>();     // stage ch data resident
        __syncthreads();           // all warps done with buffer (ch-1)%STAGES
        if (ch + STAGES - 1 < NCH) issue(ch + STAGES - 1);

        const uint32_t base = sb + (uint32_t)(ch % STAGES) * STAGE_BYTES;
        const uint32_t aAh = base;
        const uint32_t aAl = base + BUF_BYTES;
        const uint32_t aBh = base + 2 * BUF_BYTES;
        const uint32_t aBl = base + 3 * BUF_BYTES;

#pragma unroll
        for (int ks = 0; ks < 2; ks++) {
            const int kc = ks * 16;
            uint32_t ah[4][4], al[4][4], bh[4][2], bl[4][2];
#pragma unroll
            for (int mt = 0; mt < 4; mt++) {
                const uint32_t off = (uint32_t)(((a_r + mt * 16) * SSTRIDE + kc + a_c) * 2);
                ldsm4(ah[mt], aAh + off);
                ldsm4(al[mt], aAl + off);
            }
#pragma unroll
            for (int ntp = 0; ntp < 2; ntp++) {
                const uint32_t off = (uint32_t)(((b_r + ntp * 16) * SSTRIDE + kc + b_c) * 2);
                uint32_t r[4];
                ldsm4(r, aBh + off);
                bh[ntp * 2][0] = r[0]; bh[ntp * 2][1] = r[1];
                bh[ntp * 2 + 1][0] = r[2]; bh[ntp * 2 + 1][1] = r[3];
                ldsm4(r, aBl + off);
                bl[ntp * 2][0] = r[0]; bl[ntp * 2][1] = r[1];
                bl[ntp * 2 + 1][0] = r[2]; bl[ntp * 2 + 1][1] = r[3];
            }
#pragma unroll
            for (int mt = 0; mt < 4; mt++) {
#pragma unroll
                for (int nt = 0; nt < 4; nt++) {
                    mma16816(acc[mt][nt], ah[mt], bh[nt]);
                    mma16816(acc[mt][nt], ah[mt], bl[nt]);
                    mma16816(acc[mt][nt], al[mt], bh[nt]);
                }
            }
        }
    }

    // epilogue
#pragma unroll
    for (int mt = 0; mt < 4; mt++) {
        const int r0 = bm + warp_m + mt * 16 + (lane >> 2);
#pragma unroll
        for (int nt = 0; nt < 4; nt++) {
            const int col = bn + warp_n + nt * 8 + (lane & 3) * 2;
            const float b0 = bias[col], b1 = bias[col + 1];
            const float* c = acc[mt][nt];
            const size_t o0 = (size_t)r0 * N + col;
            const size_t o1 = (size_t)(r0 + 8) * N + col;
            float2 v0 = make_float2(c[0] + b0, c[1] + b1);
            float2 v1 = make_float2(c[2] + b0, c[3] + b1);
            if (add != nullptr) {
                const float2 a0 = *(const float2*)&add[o0];
                const float2 a1 = *(const float2*)&add[o1];
                v0.x += a0.x; v0.y += a0.y;
                v1.x += a1.x; v1.y += a1.y;
            }
            *(float2*)&C[o0] = v0;
            *(float2*)&C[o1] = v1;
        }
    }
}

// ---------------------------------------------------------------------------
// Flash-style causal attention with ALiBi (unchanged, fp32).
// ---------------------------------------------------------------------------
__global__ __launch_bounds__(256, 2)
void attn_kernel(const float* __restrict__ qkv, const float* __restrict__ alibi,
                 float* __restrict__ ctx)
{
    __shared__ float Ks[32][HDIM];
    __shared__ float Vs[32][HDIM];

    const int h   = blockIdx.y;
    const int qb  = blockIdx.x;
    const int tid = threadIdx.x;
    const int w    = tid >> 5;
    const int lane = tid & 31;
    const int qq = lane >> 2;
    const int g  = lane & 3;
    const int q  = qb * 64 + w * 8 + qq;

    const float* qrow = qkv + (size_t)q * QKV_N + h * 384 + g * 32;
    float qreg[32];
#pragma unroll
    for (int d = 0; d < 32; d += 4) {
        const float4 v4 = *(const float4*)(qrow + d);
        qreg[d + 0] = v4.x * INV_NORM;
        qreg[d + 1] = v4.y * INV_NORM;
        qreg[d + 2] = v4.z * INV_NORM;
        qreg[d + 3] = v4.w * INV_NORM;
    }

    float acc[32];
#pragma unroll
    for (int d = 0; d < 32; d++) acc[d] = 0.0f;
    float mrun = -INFINITY;
    float lrun = 0.0f;

    const float* alibi_h = alibi + (size_t)h * SEQ;
    const int kv_end = qb * 64 + 64;

    for (int kb = 0; kb < kv_end; kb += 32) {
        for (int i = tid; i < 32 * HDIM; i += 256) {
            const int r = i >> 7, c = i & 127;
            const float* base = qkv + (size_t)(kb + r) * QKV_N + h * 384;
            Ks[r][c] = base[128 + c];
            Vs[r][c] = base[256 + c];
        }
        __syncthreads();

#pragma unroll 1
        for (int jc = 0; jc < 32; jc += 8) {
            float s[8];
#pragma unroll
            for (int jj = 0; jj < 8; jj++) s[jj] = 0.0f;

#pragma unroll
            for (int d = 0; d < 32; d += 4) {
#pragma unroll
                for (int jj = 0; jj < 8; jj++) {
                    const float4 k4 = *(const float4*)&Ks[jc + jj][g * 32 + d];
                    s[jj] += qreg[d] * k4.x + qreg[d + 1] * k4.y
                           + qreg[d + 2] * k4.z + qreg[d + 3] * k4.w;
                }
            }
#pragma unroll
            for (int jj = 0; jj < 8; jj++) {
                s[jj] += __shfl_xor_sync(0xffffffffu, s[jj], 1);
                s[jj] += __shfl_xor_sync(0xffffffffu, s[jj], 2);
            }
            float mloc = -INFINITY;
#pragma unroll
            for (int jj = 0; jj < 8; jj++) {
                const int jg = kb + jc + jj;
                s[jj] = (jg <= q) ? (s[jj] + alibi_h[jg]) : -INFINITY;
                mloc = fmaxf(mloc, s[jj]);
            }
            if (mloc > mrun) {
                const float scale = __expf(mrun - mloc);
                mrun = mloc;
                lrun *= scale;
#pragma unroll
                for (int d = 0; d < 32; d++) acc[d] *= scale;
            }
#pragma unroll
            for (int jj = 0; jj < 8; jj++) {
                const float p = __expf(s[jj] - mrun);
                lrun += p;
#pragma unroll
                for (int d = 0; d < 32; d += 4) {
                    const float4 v4 = *(const float4*)&Vs[jc + jj][g * 32 + d];
                    acc[d + 0] += p * v4.x;
                    acc[d + 1] += p * v4.y;
                    acc[d + 2] += p * v4.z;
                    acc[d + 3] += p * v4.w;
                }
            }
        }
        __syncthreads();
    }

    const float inv_l = 1.0f / lrun;
    float* out = ctx + (size_t)q * HID + h * HDIM + g * 32;
#pragma unroll
    for (int d = 0; d < 32; d += 4) {
        float4 o = make_float4(acc[d] * inv_l, acc[d + 1] * inv_l,
                               acc[d + 2] * inv_l, acc[d + 3] * inv_l);
        *(float4*)(out + d) = o;
    }
}

// ---------------------------------------------------------------------------
// Launch
// inputs: 0 hidden_states, 1 residual, 2 alibi, 3 attention_mask (unused),
//         4 W_qkv [12288,4096], 5 b_qkv, 6 W_dense [4096,4096], 7 b_dense
// ---------------------------------------------------------------------------
extern "C" void kernel_launch(void* const* d_in, const int* in_sizes, int n_in,
                              void* d_out, int out_size)
{
    const float* hs       = (const float*)d_in[0];
    const float* residual = (const float*)d_in[1];
    const float* alibi    = (const float*)d_in[2];
    const float* Wqkv     = (const float*)d_in[4];
    const float* bqkv     = (const float*)d_in[5];
    const float* Wd       = (const float*)d_in[6];
    const float* bd       = (const float*)d_in[7];
    float* out = (float*)d_out;

    float *qkv_buf, *ctx_buf;
    __nv_bfloat16 *wq_hi, *wq_lo, *wd_hi, *wd_lo, *a_hi, *a_lo;
    cudaGetSymbolAddress((void**)&qkv_buf, g_qkv);
    cudaGetSymbolAddress((void**)&ctx_buf, g_ctx);
    cudaGetSymbolAddress((void**)&wq_hi, g_Wqkv_hi);
    cudaGetSymbolAddress((void**)&wq_lo, g_Wqkv_lo);
    cudaGetSymbolAddress((void**)&wd_hi, g_Wd_hi);
    cudaGetSymbolAddress((void**)&wd_lo, g_Wd_lo);
    cudaGetSymbolAddress((void**)&a_hi, g_A_hi);
    cudaGetSymbolAddress((void**)&a_lo, g_A_lo);

    cudaFuncSetAttribute(gemm_hmma, cudaFuncAttributeMaxDynamicSharedMemorySize, GSM_TOTAL);

    // 0) split inputs into hi/lo bf16
    split_kernel<<<2048, 256>>>(Wqkv, wq_hi, wq_lo, QKV_N * HID);
    split_kernel<<<2048, 256>>>(Wd, wd_hi, wd_lo, HID * HID);
    split_kernel<<<1024, 256>>>(hs, a_hi, a_lo, SEQ * HID);

    // 1) fused QKV projection: [2048,4096] @ [12288,4096]^T + b_qkv
    {
        dim3 grid(QKV_N / 128, SEQ / 128);
        gemm_hmma<<<grid, 256, GSM_TOTAL>>>(a_hi, a_lo, wq_hi, wq_lo, bqkv, nullptr,
                                            qkv_buf, SEQ, QKV_N, HID);
    }
    // 2) attention
    {
        dim3 grid(SEQ / 64, NHEAD);
        attn_kernel<<<grid, 256>>>(qkv_buf, alibi, ctx_buf);
    }
    // 2b) split ctx for dense GEMM
    split_kernel<<<1024, 256>>>(ctx_buf, a_hi, a_lo, SEQ * HID);

    // 3) dense projection + bias + residual
    {
        dim3 grid(HID / 128, SEQ / 128);
        gemm_hmma<<<grid, 256, GSM_TOTAL>>>(a_hi, a_lo, wd_hi, wd_lo, bd, residual,
                                            out, SEQ, HID, HID);
    }
}

// round 8
// speedup vs baseline: 1.0365x; 1.0365x over previous
#include <cuda_runtime.h>
#include <cuda_bf16.h>
#include <math.h>
#include <stdint.h>

// Problem constants (B=1)
#define SEQ   2048
#define HID   4096
#define NHEAD 32
#define HDIM  128
#define QKV_N 12288            // 3*HID
#define INV_NORM 0.08838834764831845f   // 1/sqrt(128)

// Scratch buffers (device globals; runtime alloc forbidden)
static __device__ float g_qkv[(size_t)SEQ * QKV_N];          // [S, NH*3*HD]
static __device__ float g_ctx[(size_t)SEQ * HID];            // [S, NH*HD]
static __device__ __nv_bfloat16 g_Wqkv_hi[(size_t)QKV_N * HID];
static __device__ __nv_bfloat16 g_Wqkv_lo[(size_t)QKV_N * HID];
static __device__ __nv_bfloat16 g_Wd_hi[(size_t)HID * HID];
static __device__ __nv_bfloat16 g_Wd_lo[(size_t)HID * HID];
static __device__ __nv_bfloat16 g_A_hi[(size_t)SEQ * HID];
static __device__ __nv_bfloat16 g_A_lo[(size_t)SEQ * HID];

// ---------------------------------------------------------------------------
// helpers
// ---------------------------------------------------------------------------
__device__ __forceinline__ uint32_t smem_u32(const void* p) {
    uint32_t a;
    asm("{ .reg .u64 t; cvta.to.shared.u64 t, %1; cvt.u32.u64 %0, t; }" : "=r"(a) : "l"(p));
    return a;
}
__device__ __forceinline__ void ldsm4(uint32_t* r, uint32_t addr) {
    asm volatile("ldmatrix.sync.aligned.m8n8.x4.shared.b16 {%0,%1,%2,%3}, [%4];"
                 : "=r"(r[0]), "=r"(r[1]), "=r"(r[2]), "=r"(r[3]) : "r"(addr));
}
__device__ __forceinline__ void mma16816(float* c, const uint32_t* a, const uint32_t* b) {
    asm volatile(
        "mma.sync.aligned.m16n8k16.row.col.f32.bf16.bf16.f32 "
        "{%0,%1,%2,%3}, {%4,%5,%6,%7}, {%8,%9}, {%0,%1,%2,%3};"
        : "+f"(c[0]), "+f"(c[1]), "+f"(c[2]), "+f"(c[3])
        : "r"(a[0]), "r"(a[1]), "r"(a[2]), "r"(a[3]), "r"(b[0]), "r"(b[1]));
}
__device__ __forceinline__ void cp16(uint32_t dst, const void* src) {
    asm volatile("cp.async.cg.shared.global [%0], [%1], 16;" :: "r"(dst), "l"(src) : "memory");
}
__device__ __forceinline__ void cp_commit() {
    asm volatile("cp.async.commit_group;" ::: "memory");
}
template <int N>
__device__ __forceinline__ void cp_wait() {
    asm volatile("cp.async.wait_group %0;" :: "n"(N) : "memory");
}

// ---------------------------------------------------------------------------
// fp32 -> (hi, lo) bf16 split, elementwise (grid-stride, float4)
// ---------------------------------------------------------------------------
__global__ void split_kernel(const float* __restrict__ x, __nv_bfloat16* __restrict__ hi,
                             __nv_bfloat16* __restrict__ lo, int n)
{
    const int stride = gridDim.x * blockDim.x * 4;
    for (int i = (blockIdx.x * blockDim.x + threadIdx.x) * 4; i < n; i += stride) {
        const float4 v = *(const float4*)(x + i);
        __nv_bfloat162 h0 = __floats2bfloat162_rn(v.x, v.y);
        __nv_bfloat162 h1 = __floats2bfloat162_rn(v.z, v.w);
        __nv_bfloat162 l0 = __floats2bfloat162_rn(v.x - __bfloat162float(h0.x),
                                                  v.y - __bfloat162float(h0.y));
        __nv_bfloat162 l1 = __floats2bfloat162_rn(v.z - __bfloat162float(h1.x),
                                                  v.w - __bfloat162float(h1.y));
        *(uint2*)(hi + i) = make_uint2(*(uint32_t*)&h0, *(uint32_t*)&h1);
        *(uint2*)(lo + i) = make_uint2(*(uint32_t*)&l0, *(uint32_t*)&l1);
    }
}

// ---------------------------------------------------------------------------
// Split-bf16 HMMA TN GEMM, cp.async 3-stage pipeline, 512 threads (16 warps).
// C[m,n] = sum_k A[m,k]*B[n,k] + bias[n] (+ add[m,n])
// CTA tile 128x128, BK=32, warp grid 4m x 4n, warp tile 32x32.
// smem rows padded to 40 bf16 (80B) -> conflict-free ldmatrix.
// ---------------------------------------------------------------------------
#define SSTRIDE 40
#define STAGES 3
#define BK 32
#define BUF_BYTES (128 * SSTRIDE * 2)        // 10240
#define STAGE_BYTES (4 * BUF_BYTES)          // 40960: Ah, Al, Bh, Bl
#define GSM_TOTAL (STAGES * STAGE_BYTES)     // 122880

__global__ __launch_bounds__(512, 1)
void gemm_hmma(const __nv_bfloat16* __restrict__ Ahg, const __nv_bfloat16* __restrict__ Alg,
               const __nv_bfloat16* __restrict__ Bhg, const __nv_bfloat16* __restrict__ Blg,
               const float* __restrict__ bias, const float* __restrict__ add,
               float* __restrict__ C, int M, int N, int K)
{
    extern __shared__ char smem[];
    const uint32_t sb = smem_u32(smem);

    const int tid  = threadIdx.x;
    const int wid  = tid >> 5;
    const int lane = tid & 31;
    const int bm = blockIdx.y * 128;
    const int bn = blockIdx.x * 128;

    const int warp_m = (wid & 3) * 32;     // 4 warps along M
    const int warp_n = (wid >> 2) * 32;    // 4 warps along N

    // loader mapping: thread -> row (0..127), 8-col quarter of the 32-col chunk
    const int lrow = tid >> 2;
    const int lcol = (tid & 3) * 8;
    const __nv_bfloat16* gAh = Ahg + (size_t)(bm + lrow) * K + lcol;
    const __nv_bfloat16* gAl = Alg + (size_t)(bm + lrow) * K + lcol;
    const __nv_bfloat16* gBh = Bhg + (size_t)(bn + lrow) * K + lcol;
    const __nv_bfloat16* gBl = Blg + (size_t)(bn + lrow) * K + lcol;
    const uint32_t sdst = (uint32_t)(lrow * SSTRIDE + lcol) * 2;

    // ldmatrix lane addressing (validated in R5)
    const int a_r = warp_m + (lane & 15);
    const int a_c = (lane >> 4) * 8;
    const int b_r = warp_n + (lane >> 4) * 8 + (lane & 7);
    const int b_c = ((lane >> 3) & 1) * 8;

    float acc[2][4][4];
#pragma unroll
    for (int i = 0; i < 2; i++)
#pragma unroll
        for (int j = 0; j < 4; j++)
#pragma unroll
            for (int e = 0; e < 4; e++) acc[i][j][e] = 0.0f;

    const int NCH = K >> 5;

    // issue one stage's loads (4 x cp.async of 16B per thread)
    auto issue = [&](int ch) {
        const uint32_t base = sb + (uint32_t)(ch % STAGES) * STAGE_BYTES;
        const int ko = ch * BK;
        cp16(base + sdst,                  gAh + ko);
        cp16(base + BUF_BYTES + sdst,      gAl + ko);
        cp16(base + 2 * BUF_BYTES + sdst,  gBh + ko);
        cp16(base + 3 * BUF_BYTES + sdst,  gBl + ko);
        cp_commit();
    };

#pragma unroll
    for (int ch = 0; ch < STAGES - 1; ch++) issue(ch);

    for (int ch = 0; ch < NCH; ch++) {
        cp_wait<STAGES - 2>();
        __syncthreads();
        if (ch + STAGES - 1 < NCH) issue(ch + STAGES - 1);

        const uint32_t base = sb + (uint32_t)(ch % STAGES) * STAGE_BYTES;
        const uint32_t aAh = base;
        const uint32_t aAl = base + BUF_BYTES;
        const uint32_t aBh = base + 2 * BUF_BYTES;
        const uint32_t aBl = base + 3 * BUF_BYTES;

#pragma unroll
        for (int ks = 0; ks < 2; ks++) {
            const int kc = ks * 16;
            uint32_t ah[2][4], al[2][4], bh[4][2], bl[4][2];
#pragma unroll
            for (int mt = 0; mt < 2; mt++) {
                const uint32_t off = (uint32_t)(((a_r + mt * 16) * SSTRIDE + kc + a_c) * 2);
                ldsm4(ah[mt], aAh + off);
                ldsm4(al[mt], aAl + off);
            }
#pragma unroll
            for (int ntp = 0; ntp < 2; ntp++) {
                const uint32_t off = (uint32_t)(((b_r + ntp * 16) * SSTRIDE + kc + b_c) * 2);
                uint32_t r[4];
                ldsm4(r, aBh + off);
                bh[ntp * 2][0] = r[0]; bh[ntp * 2][1] = r[1];
                bh[ntp * 2 + 1][0] = r[2]; bh[ntp * 2 + 1][1] = r[3];
                ldsm4(r, aBl + off);
                bl[ntp * 2][0] = r[0]; bl[ntp * 2][1] = r[1];
                bl[ntp * 2 + 1][0] = r[2]; bl[ntp * 2 + 1][1] = r[3];
            }
#pragma unroll
            for (int mt = 0; mt < 2; mt++) {
#pragma unroll
                for (int nt = 0; nt < 4; nt++) {
                    mma16816(acc[mt][nt], ah[mt], bh[nt]);
                    mma16816(acc[mt][nt], ah[mt], bl[nt]);
                    mma16816(acc[mt][nt], al[mt], bh[nt]);
                }
            }
        }
    }

    // epilogue
#pragma unroll
    for (int mt = 0; mt < 2; mt++) {
        const int r0 = bm + warp_m + mt * 16 + (lane >> 2);
#pragma unroll
        for (int nt = 0; nt < 4; nt++) {
            const int col = bn + warp_n + nt * 8 + (lane & 3) * 2;
            const float b0 = bias[col], b1 = bias[col + 1];
            const float* c = acc[mt][nt];
            const size_t o0 = (size_t)r0 * N + col;
            const size_t o1 = (size_t)(r0 + 8) * N + col;
            float2 v0 = make_float2(c[0] + b0, c[1] + b1);
            float2 v1 = make_float2(c[2] + b0, c[3] + b1);
            if (add != nullptr) {
                const float2 a0 = *(const float2*)&add[o0];
                const float2 a1 = *(const float2*)&add[o1];
                v0.x += a0.x; v0.y += a0.y;
                v1.x += a1.x; v1.y += a1.y;
            }
            *(float2*)&C[o0] = v0;
            *(float2*)&C[o1] = v1;
        }
    }
}

// ---------------------------------------------------------------------------
// Flash-style causal attention with ALiBi (unchanged, fp32).
// ---------------------------------------------------------------------------
__global__ __launch_bounds__(256, 2)
void attn_kernel(const float* __restrict__ qkv, const float* __restrict__ alibi,
                 float* __restrict__ ctx)
{
    __shared__ float Ks[32][HDIM];
    __shared__ float Vs[32][HDIM];

    const int h   = blockIdx.y;
    const int qb  = blockIdx.x;
    const int tid = threadIdx.x;
    const int w    = tid >> 5;
    const int lane = tid & 31;
    const int qq = lane >> 2;
    const int g  = lane & 3;
    const int q  = qb * 64 + w * 8 + qq;

    const float* qrow = qkv + (size_t)q * QKV_N + h * 384 + g * 32;
    float qreg[32];
#pragma unroll
    for (int d = 0; d < 32; d += 4) {
        const float4 v4 = *(const float4*)(qrow + d);
        qreg[d + 0] = v4.x * INV_NORM;
        qreg[d + 1] = v4.y * INV_NORM;
        qreg[d + 2] = v4.z * INV_NORM;
        qreg[d + 3] = v4.w * INV_NORM;
    }

    float acc[32];
#pragma unroll
    for (int d = 0; d < 32; d++) acc[d] = 0.0f;
    float mrun = -INFINITY;
    float lrun = 0.0f;

    const float* alibi_h = alibi + (size_t)h * SEQ;
    const int kv_end = qb * 64 + 64;

    for (int kb = 0; kb < kv_end; kb += 32) {
        for (int i = tid; i < 32 * HDIM; i += 256) {
            const int r = i >> 7, c = i & 127;
            const float* base = qkv + (size_t)(kb + r) * QKV_N + h * 384;
            Ks[r][c] = base[128 + c];
            Vs[r][c] = base[256 + c];
        }
        __syncthreads();

#pragma unroll 1
        for (int jc = 0; jc < 32; jc += 8) {
            float s[8];
#pragma unroll
            for (int jj = 0; jj < 8; jj++) s[jj] = 0.0f;

#pragma unroll
            for (int d = 0; d < 32; d += 4) {
#pragma unroll
                for (int jj = 0; jj < 8; jj++) {
                    const float4 k4 = *(const float4*)&Ks[jc + jj][g * 32 + d];
                    s[jj] += qreg[d] * k4.x + qreg[d + 1] * k4.y
                           + qreg[d + 2] * k4.z + qreg[d + 3] * k4.w;
                }
            }
#pragma unroll
            for (int jj = 0; jj < 8; jj++) {
                s[jj] += __shfl_xor_sync(0xffffffffu, s[jj], 1);
                s[jj] += __shfl_xor_sync(0xffffffffu, s[jj], 2);
            }
            float mloc = -INFINITY;
#pragma unroll
            for (int jj = 0; jj < 8; jj++) {
                const int jg = kb + jc + jj;
                s[jj] = (jg <= q) ? (s[jj] + alibi_h[jg]) : -INFINITY;
                mloc = fmaxf(mloc, s[jj]);
            }
            if (mloc > mrun) {
                const float scale = __expf(mrun - mloc);
                mrun = mloc;
                lrun *= scale;
#pragma unroll
                for (int d = 0; d < 32; d++) acc[d] *= scale;
            }
#pragma unroll
            for (int jj = 0; jj < 8; jj++) {
                const float p = __expf(s[jj] - mrun);
                lrun += p;
#pragma unroll
                for (int d = 0; d < 32; d += 4) {
                    const float4 v4 = *(const float4*)&Vs[jc + jj][g * 32 + d];
                    acc[d + 0] += p * v4.x;
                    acc[d + 1] += p * v4.y;
                    acc[d + 2] += p * v4.z;
                    acc[d + 3] += p * v4.w;
                }
            }
        }
        __syncthreads();
    }

    const float inv_l = 1.0f / lrun;
    float* out = ctx + (size_t)q * HID + h * HDIM + g * 32;
#pragma unroll
    for (int d = 0; d < 32; d += 4) {
        float4 o = make_float4(acc[d] * inv_l, acc[d + 1] * inv_l,
                               acc[d + 2] * inv_l, acc[d + 3] * inv_l);
        *(float4*)(out + d) = o;
    }
}

// ---------------------------------------------------------------------------
// Launch
// inputs: 0 hidden_states, 1 residual, 2 alibi, 3 attention_mask (unused),
//         4 W_qkv [12288,4096], 5 b_qkv, 6 W_dense [4096,4096], 7 b_dense
// ---------------------------------------------------------------------------
extern "C" void kernel_launch(void* const* d_in, const int* in_sizes, int n_in,
                              void* d_out, int out_size)
{
    const float* hs       = (const float*)d_in[0];
    const float* residual = (const float*)d_in[1];
    const float* alibi    = (const float*)d_in[2];
    const float* Wqkv     = (const float*)d_in[4];
    const float* bqkv     = (const float*)d_in[5];
    const float* Wd       = (const float*)d_in[6];
    const float* bd       = (const float*)d_in[7];
    float* out = (float*)d_out;

    float *qkv_buf, *ctx_buf;
    __nv_bfloat16 *wq_hi, *wq_lo, *wd_hi, *wd_lo, *a_hi, *a_lo;
    cudaGetSymbolAddress((void**)&qkv_buf, g_qkv);
    cudaGetSymbolAddress((void**)&ctx_buf, g_ctx);
    cudaGetSymbolAddress((void**)&wq_hi, g_Wqkv_hi);
    cudaGetSymbolAddress((void**)&wq_lo, g_Wqkv_lo);
    cudaGetSymbolAddress((void**)&wd_hi, g_Wd_hi);
    cudaGetSymbolAddress((void**)&wd_lo, g_Wd_lo);
    cudaGetSymbolAddress((void**)&a_hi, g_A_hi);
    cudaGetSymbolAddress((void**)&a_lo, g_A_lo);

    cudaFuncSetAttribute(gemm_hmma, cudaFuncAttributeMaxDynamicSharedMemorySize, GSM_TOTAL);

    // 0) split inputs into hi/lo bf16
    split_kernel<<<2048, 256>>>(Wqkv, wq_hi, wq_lo, QKV_N * HID);
    split_kernel<<<2048, 256>>>(Wd, wd_hi, wd_lo, HID * HID);
    split_kernel<<<1024, 256>>>(hs, a_hi, a_lo, SEQ * HID);

    // 1) fused QKV projection: [2048,4096] @ [12288,4096]^T + b_qkv
    {
        dim3 grid(QKV_N / 128, SEQ / 128);
        gemm_hmma<<<grid, 512, GSM_TOTAL>>>(a_hi, a_lo, wq_hi, wq_lo, bqkv, nullptr,
                                            qkv_buf, SEQ, QKV_N, HID);
    }
    // 2) attention
    {
        dim3 grid(SEQ / 64, NHEAD);
        attn_kernel<<<grid, 256>>>(qkv_buf, alibi, ctx_buf);
    }
    // 2b) split ctx for dense GEMM
    split_kernel<<<1024, 256>>>(ctx_buf, a_hi, a_lo, SEQ * HID);

    // 3) dense projection + bias + residual
    {
        dim3 grid(HID / 128, SEQ / 128);
        gemm_hmma<<<grid, 512, GSM_TOTAL>>>(a_hi, a_lo, wd_hi, wd_lo, bd, residual,
                                            out, SEQ, HID, HID);
    }
}

// round 9
// speedup vs baseline: 1.1163x; 1.0770x over previous
#include <cuda_runtime.h>
#include <cuda_fp16.h>
#include <math.h>
#include <stdint.h>

// Problem constants (B=1)
#define SEQ   2048
#define HID   4096
#define NHEAD 32
#define HDIM  128
#define QKV_N 12288            // 3*HID
#define INV_NORM 0.08838834764831845f   // 1/sqrt(128)

// Scratch buffers (device globals; runtime alloc forbidden)
static __device__ float g_qkv[(size_t)SEQ * QKV_N];          // [S, NH*3*HD]
static __device__ float g_ctx[(size_t)SEQ * HID];            // [S, NH*HD]
static __device__ __half g_Wqkv_h[(size_t)QKV_N * HID];
static __device__ __half g_Wd_h[(size_t)HID * HID];
static __device__ __half g_A_hi[(size_t)SEQ * HID];
static __device__ __half g_A_lo[(size_t)SEQ * HID];

// ---------------------------------------------------------------------------
// helpers
// ---------------------------------------------------------------------------
__device__ __forceinline__ uint32_t smem_u32(const void* p) {
    uint32_t a;
    asm("{ .reg .u64 t; cvta.to.shared.u64 t, %1; cvt.u32.u64 %0, t; }" : "=r"(a) : "l"(p));
    return a;
}
__device__ __forceinline__ void ldsm4(uint32_t* r, uint32_t addr) {
    asm volatile("ldmatrix.sync.aligned.m8n8.x4.shared.b16 {%0,%1,%2,%3}, [%4];"
                 : "=r"(r[0]), "=r"(r[1]), "=r"(r[2]), "=r"(r[3]) : "r"(addr));
}
__device__ __forceinline__ void mma16816(float* c, const uint32_t* a, const uint32_t* b) {
    asm volatile(
        "mma.sync.aligned.m16n8k16.row.col.f32.f16.f16.f32 "
        "{%0,%1,%2,%3}, {%4,%5,%6,%7}, {%8,%9}, {%0,%1,%2,%3};"
        : "+f"(c[0]), "+f"(c[1]), "+f"(c[2]), "+f"(c[3])
        : "r"(a[0]), "r"(a[1]), "r"(a[2]), "r"(a[3]), "r"(b[0]), "r"(b[1]));
}
__device__ __forceinline__ void cp16(uint32_t dst, const void* src) {
    asm volatile("cp.async.cg.shared.global [%0], [%1], 16;" :: "r"(dst), "l"(src) : "memory");
}
__device__ __forceinline__ void cp_commit() {
    asm volatile("cp.async.commit_group;" ::: "memory");
}
template <int N>
__device__ __forceinline__ void cp_wait() {
    asm volatile("cp.async.wait_group %0;" :: "n"(N) : "memory");
}

// ---------------------------------------------------------------------------
// fp32 -> (hi, lo) fp16 exact 2-term split (grid-stride, float4)
// ---------------------------------------------------------------------------
__global__ void splitA_kernel(const float* __restrict__ x, __half* __restrict__ hi,
                              __half* __restrict__ lo, int n)
{
    const int stride = gridDim.x * blockDim.x * 4;
    for (int i = (blockIdx.x * blockDim.x + threadIdx.x) * 4; i < n; i += stride) {
        const float4 v = *(const float4*)(x + i);
        __half2 h0 = __floats2half2_rn(v.x, v.y);
        __half2 h1 = __floats2half2_rn(v.z, v.w);
        __half2 l0 = __floats2half2_rn(v.x - __half2float(h0.x),
                                       v.y - __half2float(h0.y));
        __half2 l1 = __floats2half2_rn(v.z - __half2float(h1.x),
                                       v.w - __half2float(h1.y));
        *(uint2*)(hi + i) = make_uint2(*(uint32_t*)&h0, *(uint32_t*)&h1);
        *(uint2*)(lo + i) = make_uint2(*(uint32_t*)&l0, *(uint32_t*)&l1);
    }
}

// fp32 -> fp16 round (weights)
__global__ void roundB_kernel(const float* __restrict__ x, __half* __restrict__ h, int n)
{
    const int stride = gridDim.x * blockDim.x * 4;
    for (int i = (blockIdx.x * blockDim.x + threadIdx.x) * 4; i < n; i += stride) {
        const float4 v = *(const float4*)(x + i);
        __half2 h0 = __floats2half2_rn(v.x, v.y);
        __half2 h1 = __floats2half2_rn(v.z, v.w);
        *(uint2*)(h + i) = make_uint2(*(uint32_t*)&h0, *(uint32_t*)&h1);
    }
}

// ---------------------------------------------------------------------------
// 2-term fp16 HMMA TN GEMM, cp.async 3-stage pipeline, 512 threads (16 warps).
// C[m,n] = sum_k A[m,k]*Bh[n,k] + bias[n] (+ add[m,n]),  A = Ah + Al (fp16 pair)
// CTA tile 128x128, BK=32, warp grid 4m x 4n, warp tile 32x32.
// smem rows padded to 40 halves (80B) -> conflict-free ldmatrix.
// ---------------------------------------------------------------------------
#define SSTRIDE 40
#define STAGES 3
#define BK 32
#define BUF_BYTES (128 * SSTRIDE * 2)        // 10240
#define STAGE_BYTES (3 * BUF_BYTES)          // 30720: Ah, Al, Bh
#define GSM_TOTAL (STAGES * STAGE_BYTES)     // 92160

__global__ __launch_bounds__(512, 1)
void gemm_hmma(const __half* __restrict__ Ahg, const __half* __restrict__ Alg,
               const __half* __restrict__ Bhg,
               const float* __restrict__ bias, const float* __restrict__ add,
               float* __restrict__ C, int M, int N, int K)
{
    extern __shared__ char smem[];
    const uint32_t sb = smem_u32(smem);

    const int tid  = threadIdx.x;
    const int wid  = tid >> 5;
    const int lane = tid & 31;
    const int bm = blockIdx.y * 128;
    const int bn = blockIdx.x * 128;

    const int warp_m = (wid & 3) * 32;     // 4 warps along M
    const int warp_n = (wid >> 2) * 32;    // 4 warps along N

    // loader mapping: thread -> row (0..127), 8-col quarter of the 32-col chunk
    const int lrow = tid >> 2;
    const int lcol = (tid & 3) * 8;
    const __half* gAh = Ahg + (size_t)(bm + lrow) * K + lcol;
    const __half* gAl = Alg + (size_t)(bm + lrow) * K + lcol;
    const __half* gBh = Bhg + (size_t)(bn + lrow) * K + lcol;
    const uint32_t sdst = (uint32_t)(lrow * SSTRIDE + lcol) * 2;

    // ldmatrix lane addressing (validated R5/R8)
    const int a_r = warp_m + (lane & 15);
    const int a_c = (lane >> 4) * 8;
    const int b_r = warp_n + (lane >> 4) * 8 + (lane & 7);
    const int b_c = ((lane >> 3) & 1) * 8;

    float acc[2][4][4];
#pragma unroll
    for (int i = 0; i < 2; i++)
#pragma unroll
        for (int j = 0; j < 4; j++)
#pragma unroll
            for (int e = 0; e < 4; e++) acc[i][j][e] = 0.0f;

    const int NCH = K >> 5;

    auto issue = [&](int ch) {
        const uint32_t base = sb + (uint32_t)(ch % STAGES) * STAGE_BYTES;
        const int ko = ch * BK;
        cp16(base + sdst,                  gAh + ko);
        cp16(base + BUF_BYTES + sdst,      gAl + ko);
        cp16(base + 2 * BUF_BYTES + sdst,  gBh + ko);
        cp_commit();
    };

#pragma unroll
    for (int ch = 0; ch < STAGES - 1; ch++) issue(ch);

    for (int ch = 0; ch < NCH; ch++) {
        cp_wait<STAGES - 2>();
        __syncthreads();
        if (ch + STAGES - 1 < NCH) issue(ch + STAGES - 1);

        const uint32_t base = sb + (uint32_t)(ch % STAGES) * STAGE_BYTES;
        const uint32_t aAh = base;
        const uint32_t aAl = base + BUF_BYTES;
        const uint32_t aBh = base + 2 * BUF_BYTES;

#pragma unroll
        for (int ks = 0; ks < 2; ks++) {
            const int kc = ks * 16;
            uint32_t ah[2][4], al[2][4], bh[4][2];
#pragma unroll
            for (int mt = 0; mt < 2; mt++) {
                const uint32_t off = (uint32_t)(((a_r + mt * 16) * SSTRIDE + kc + a_c) * 2);
                ldsm4(ah[mt], aAh + off);
                ldsm4(al[mt], aAl + off);
            }
#pragma unroll
            for (int ntp = 0; ntp < 2; ntp++) {
                const uint32_t off = (uint32_t)(((b_r + ntp * 16) * SSTRIDE + kc + b_c) * 2);
                uint32_t r[4];
                ldsm4(r, aBh + off);
                bh[ntp * 2][0] = r[0]; bh[ntp * 2][1] = r[1];
                bh[ntp * 2 + 1][0] = r[2]; bh[ntp * 2 + 1][1] = r[3];
            }
#pragma unroll
            for (int mt = 0; mt < 2; mt++) {
#pragma unroll
                for (int nt = 0; nt < 4; nt++) {
                    mma16816(acc[mt][nt], ah[mt], bh[nt]);
                    mma16816(acc[mt][nt], al[mt], bh[nt]);
                }
            }
        }
    }

    // epilogue
#pragma unroll
    for (int mt = 0; mt < 2; mt++) {
        const int r0 = bm + warp_m + mt * 16 + (lane >> 2);
#pragma unroll
        for (int nt = 0; nt < 4; nt++) {
            const int col = bn + warp_n + nt * 8 + (lane & 3) * 2;
            const float b0 = bias[col], b1 = bias[col + 1];
            const float* c = acc[mt][nt];
            const size_t o0 = (size_t)r0 * N + col;
            const size_t o1 = (size_t)(r0 + 8) * N + col;
            float2 v0 = make_float2(c[0] + b0, c[1] + b1);
            float2 v1 = make_float2(c[2] + b0, c[3] + b1);
            if (add != nullptr) {
                const float2 a0 = *(const float2*)&add[o0];
                const float2 a1 = *(const float2*)&add[o1];
                v0.x += a0.x; v0.y += a0.y;
                v1.x += a1.x; v1.y += a1.y;
            }
            *(float2*)&C[o0] = v0;
            *(float2*)&C[o1] = v1;
        }
    }
}

// ---------------------------------------------------------------------------
// Flash-style causal attention with ALiBi (unchanged, fp32).
// ---------------------------------------------------------------------------
__global__ __launch_bounds__(256, 2)
void attn_kernel(const float* __restrict__ qkv, const float* __restrict__ alibi,
                 float* __restrict__ ctx)
{
    __shared__ float Ks[32][HDIM];
    __shared__ float Vs[32][HDIM];

    const int h   = blockIdx.y;
    const int qb  = blockIdx.x;
    const int tid = threadIdx.x;
    const int w    = tid >> 5;
    const int lane = tid & 31;
    const int qq = lane >> 2;
    const int g  = lane & 3;
    const int q  = qb * 64 + w * 8 + qq;

    const float* qrow = qkv + (size_t)q * QKV_N + h * 384 + g * 32;
    float qreg[32];
#pragma unroll
    for (int d = 0; d < 32; d += 4) {
        const float4 v4 = *(const float4*)(qrow + d);
        qreg[d + 0] = v4.x * INV_NORM;
        qreg[d + 1] = v4.y * INV_NORM;
        qreg[d + 2] = v4.z * INV_NORM;
        qreg[d + 3] = v4.w * INV_NORM;
    }

    float acc[32];
#pragma unroll
    for (int d = 0; d < 32; d++) acc[d] = 0.0f;
    float mrun = -INFINITY;
    float lrun = 0.0f;

    const float* alibi_h = alibi + (size_t)h * SEQ;
    const int kv_end = qb * 64 + 64;

    for (int kb = 0; kb < kv_end; kb += 32) {
        for (int i = tid; i < 32 * HDIM; i += 256) {
            const int r = i >> 7, c = i & 127;
            const float* base = qkv + (size_t)(kb + r) * QKV_N + h * 384;
            Ks[r][c] = base[128 + c];
            Vs[r][c] = base[256 + c];
        }
        __syncthreads();

#pragma unroll 1
        for (int jc = 0; jc < 32; jc += 8) {
            float s[8];
#pragma unroll
            for (int jj = 0; jj < 8; jj++) s[jj] = 0.0f;

#pragma unroll
            for (int d = 0; d < 32; d += 4) {
#pragma unroll
                for (int jj = 0; jj < 8; jj++) {
                    const float4 k4 = *(const float4*)&Ks[jc + jj][g * 32 + d];
                    s[jj] += qreg[d] * k4.x + qreg[d + 1] * k4.y
                           + qreg[d + 2] * k4.z + qreg[d + 3] * k4.w;
                }
            }
#pragma unroll
            for (int jj = 0; jj < 8; jj++) {
                s[jj] += __shfl_xor_sync(0xffffffffu, s[jj], 1);
                s[jj] += __shfl_xor_sync(0xffffffffu, s[jj], 2);
            }
            float mloc = -INFINITY;
#pragma unroll
            for (int jj = 0; jj < 8; jj++) {
                const int jg = kb + jc + jj;
                s[jj] = (jg <= q) ? (s[jj] + alibi_h[jg]) : -INFINITY;
                mloc = fmaxf(mloc, s[jj]);
            }
            if (mloc > mrun) {
                const float scale = __expf(mrun - mloc);
                mrun = mloc;
                lrun *= scale;
#pragma unroll
                for (int d = 0; d < 32; d++) acc[d] *= scale;
            }
#pragma unroll
            for (int jj = 0; jj < 8; jj++) {
                const float p = __expf(s[jj] - mrun);
                lrun += p;
#pragma unroll
                for (int d = 0; d < 32; d += 4) {
                    const float4 v4 = *(const float4*)&Vs[jc + jj][g * 32 + d];
                    acc[d + 0] += p * v4.x;
                    acc[d + 1] += p * v4.y;
                    acc[d + 2] += p * v4.z;
                    acc[d + 3] += p * v4.w;
                }
            }
        }
        __syncthreads();
    }

    const float inv_l = 1.0f / lrun;
    float* out = ctx + (size_t)q * HID + h * HDIM + g * 32;
#pragma unroll
    for (int d = 0; d < 32; d += 4) {
        float4 o = make_float4(acc[d] * inv_l, acc[d + 1] * inv_l,
                               acc[d + 2] * inv_l, acc[d + 3] * inv_l);
        *(float4*)(out + d) = o;
    }
}

// ---------------------------------------------------------------------------
// Launch
// inputs: 0 hidden_states, 1 residual, 2 alibi, 3 attention_mask (unused),
//         4 W_qkv [12288,4096], 5 b_qkv, 6 W_dense [4096,4096], 7 b_dense
// ---------------------------------------------------------------------------
extern "C" void kernel_launch(void* const* d_in, const int* in_sizes, int n_in,
                              void* d_out, int out_size)
{
    const float* hs       = (const float*)d_in[0];
    const float* residual = (const float*)d_in[1];
    const float* alibi    = (const float*)d_in[2];
    const float* Wqkv     = (const float*)d_in[4];
    const float* bqkv     = (const float*)d_in[5];
    const float* Wd       = (const float*)d_in[6];
    const float* bd       = (const float*)d_in[7];
    float* out = (float*)d_out;

    float *qkv_buf, *ctx_buf;
    __half *wq_h, *wd_h, *a_hi, *a_lo;
    cudaGetSymbolAddress((void**)&qkv_buf, g_qkv);
    cudaGetSymbolAddress((void**)&ctx_buf, g_ctx);
    cudaGetSymbolAddress((void**)&wq_h, g_Wqkv_h);
    cudaGetSymbolAddress((void**)&wd_h, g_Wd_h);
    cudaGetSymbolAddress((void**)&a_hi, g_A_hi);
    cudaGetSymbolAddress((void**)&a_lo, g_A_lo);

    cudaFuncSetAttribute(gemm_hmma, cudaFuncAttributeMaxDynamicSharedMemorySize, GSM_TOTAL);

    // 0) convert operands
    roundB_kernel<<<2048, 256>>>(Wqkv, wq_h, QKV_N * HID);
    roundB_kernel<<<2048, 256>>>(Wd, wd_h, HID * HID);
    splitA_kernel<<<1024, 256>>>(hs, a_hi, a_lo, SEQ * HID);

    // 1) fused QKV projection: [2048,4096] @ [12288,4096]^T + b_qkv
    {
        dim3 grid(QKV_N / 128, SEQ / 128);
        gemm_hmma<<<grid, 512, GSM_TOTAL>>>(a_hi, a_lo, wq_h, bqkv, nullptr,
                                            qkv_buf, SEQ, QKV_N, HID);
    }
    // 2) attention
    {
        dim3 grid(SEQ / 64, NHEAD);
        attn_kernel<<<grid, 256>>>(qkv_buf, alibi, ctx_buf);
    }
    // 2b) split ctx for dense GEMM
    splitA_kernel<<<1024, 256>>>(ctx_buf, a_hi, a_lo, SEQ * HID);

    // 3) dense projection + bias + residual
    {
        dim3 grid(HID / 128, SEQ / 128);
        gemm_hmma<<<grid, 512, GSM_TOTAL>>>(a_hi, a_lo, wd_h, bd, residual,
                                            out, SEQ, HID, HID);
    }
}

// round 10
// speedup vs baseline: 1.1810x; 1.0580x over previous
#include <cuda_runtime.h>
#include <cuda_fp16.h>
#include <math.h>
#include <stdint.h>

// Problem constants (B=1)
#define SEQ   2048
#define HID   4096
#define NHEAD 32
#define HDIM  128
#define QKV_N 12288            // 3*HID
#define INV_NORM 0.08838834764831845f   // 1/sqrt(128)

// Scratch buffers (device globals; runtime alloc forbidden)
static __device__ float g_qkv[(size_t)SEQ * QKV_N];          // [S, NH*3*HD]
static __device__ float g_ctx[(size_t)SEQ * HID];            // [S, NH*HD]
static __device__ __half g_Wqkv_h[(size_t)QKV_N * HID];
static __device__ __half g_Wd_h[(size_t)HID * HID];
static __device__ __half g_A_h[(size_t)SEQ * HID];

// ---------------------------------------------------------------------------
// helpers
// ---------------------------------------------------------------------------
__device__ __forceinline__ uint32_t smem_u32(const void* p) {
    uint32_t a;
    asm("{ .reg .u64 t; cvta.to.shared.u64 t, %1; cvt.u32.u64 %0, t; }" : "=r"(a) : "l"(p));
    return a;
}
__device__ __forceinline__ void ldsm4(uint32_t* r, uint32_t addr) {
    asm volatile("ldmatrix.sync.aligned.m8n8.x4.shared.b16 {%0,%1,%2,%3}, [%4];"
                 : "=r"(r[0]), "=r"(r[1]), "=r"(r[2]), "=r"(r[3]) : "r"(addr));
}
__device__ __forceinline__ void mma16816(float* c, const uint32_t* a, const uint32_t* b) {
    asm volatile(
        "mma.sync.aligned.m16n8k16.row.col.f32.f16.f16.f32 "
        "{%0,%1,%2,%3}, {%4,%5,%6,%7}, {%8,%9}, {%0,%1,%2,%3};"
        : "+f"(c[0]), "+f"(c[1]), "+f"(c[2]), "+f"(c[3])
        : "r"(a[0]), "r"(a[1]), "r"(a[2]), "r"(a[3]), "r"(b[0]), "r"(b[1]));
}
__device__ __forceinline__ void cp16(uint32_t dst, const void* src) {
    asm volatile("cp.async.cg.shared.global [%0], [%1], 16;" :: "r"(dst), "l"(src) : "memory");
}
__device__ __forceinline__ void cp_commit() {
    asm volatile("cp.async.commit_group;" ::: "memory");
}
template <int N>
__device__ __forceinline__ void cp_wait() {
    asm volatile("cp.async.wait_group %0;" :: "n"(N) : "memory");
}

// ---------------------------------------------------------------------------
// fp32 -> fp16 round (grid-stride, float4)
// ---------------------------------------------------------------------------
__global__ void round16_kernel(const float* __restrict__ x, __half* __restrict__ h, int n)
{
    const int stride = gridDim.x * blockDim.x * 4;
    for (int i = (blockIdx.x * blockDim.x + threadIdx.x) * 4; i < n; i += stride) {
        const float4 v = *(const float4*)(x + i);
        __half2 h0 = __floats2half2_rn(v.x, v.y);
        __half2 h1 = __floats2half2_rn(v.z, v.w);
        *(uint2*)(h + i) = make_uint2(*(uint32_t*)&h0, *(uint32_t*)&h1);
    }
}

// ---------------------------------------------------------------------------
// fp16 HMMA TN GEMM, cp.async 4-stage pipeline, 512 threads (16 warps).
// C[m,n] = sum_k A[m,k]*B[n,k] + bias[n] (+ add[m,n]),  A,B fp16, fp32 accum
// CTA tile 128x128, BK=32, warp grid 4m x 4n, warp tile 32x32.
// smem rows padded to 40 halves (80B) -> conflict-free ldmatrix.
// ---------------------------------------------------------------------------
#define SSTRIDE 40
#define STAGES 4
#define BK 32
#define BUF_BYTES (128 * SSTRIDE * 2)        // 10240
#define STAGE_BYTES (2 * BUF_BYTES)          // 20480: A, B
#define GSM_TOTAL (STAGES * STAGE_BYTES)     // 81920

__global__ __launch_bounds__(512, 1)
void gemm_hmma(const __half* __restrict__ Ag, const __half* __restrict__ Bg,
               const float* __restrict__ bias, const float* __restrict__ add,
               float* __restrict__ C, int M, int N, int K)
{
    extern __shared__ char smem[];
    const uint32_t sb = smem_u32(smem);

    const int tid  = threadIdx.x;
    const int wid  = tid >> 5;
    const int lane = tid & 31;
    const int bm = blockIdx.y * 128;
    const int bn = blockIdx.x * 128;

    const int warp_m = (wid & 3) * 32;     // 4 warps along M
    const int warp_n = (wid >> 2) * 32;    // 4 warps along N

    // loader mapping: thread -> row (0..127), 8-col quarter of the 32-col chunk
    const int lrow = tid >> 2;
    const int lcol = (tid & 3) * 8;
    const __half* gA = Ag + (size_t)(bm + lrow) * K + lcol;
    const __half* gB = Bg + (size_t)(bn + lrow) * K + lcol;
    const uint32_t sdst = (uint32_t)(lrow * SSTRIDE + lcol) * 2;

    // ldmatrix lane addressing (validated R5/R8/R9)
    const int a_r = warp_m + (lane & 15);
    const int a_c = (lane >> 4) * 8;
    const int b_r = warp_n + (lane >> 4) * 8 + (lane & 7);
    const int b_c = ((lane >> 3) & 1) * 8;

    float acc[2][4][4];
#pragma unroll
    for (int i = 0; i < 2; i++)
#pragma unroll
        for (int j = 0; j < 4; j++)
#pragma unroll
            for (int e = 0; e < 4; e++) acc[i][j][e] = 0.0f;

    const int NCH = K >> 5;

    auto issue = [&](int ch) {
        const uint32_t base = sb + (uint32_t)(ch % STAGES) * STAGE_BYTES;
        const int ko = ch * BK;
        cp16(base + sdst,             gA + ko);
        cp16(base + BUF_BYTES + sdst, gB + ko);
        cp_commit();
    };

#pragma unroll
    for (int ch = 0; ch < STAGES - 1; ch++) issue(ch);

    for (int ch = 0; ch < NCH; ch++) {
        cp_wait<STAGES - 2>();
        __syncthreads();
        if (ch + STAGES - 1 < NCH) issue(ch + STAGES - 1);

        const uint32_t base = sb + (uint32_t)(ch % STAGES) * STAGE_BYTES;
        const uint32_t aA = base;
        const uint32_t aB = base + BUF_BYTES;

#pragma unroll
        for (int ks = 0; ks < 2; ks++) {
            const int kc = ks * 16;
            uint32_t ah[2][4], bh[4][2];
#pragma unroll
            for (int mt = 0; mt < 2; mt++) {
                const uint32_t off = (uint32_t)(((a_r + mt * 16) * SSTRIDE + kc + a_c) * 2);
                ldsm4(ah[mt], aA + off);
            }
#pragma unroll
            for (int ntp = 0; ntp < 2; ntp++) {
                const uint32_t off = (uint32_t)(((b_r + ntp * 16) * SSTRIDE + kc + b_c) * 2);
                uint32_t r[4];
                ldsm4(r, aB + off);
                bh[ntp * 2][0] = r[0]; bh[ntp * 2][1] = r[1];
                bh[ntp * 2 + 1][0] = r[2]; bh[ntp * 2 + 1][1] = r[3];
            }
#pragma unroll
            for (int mt = 0; mt < 2; mt++) {
#pragma unroll
                for (int nt = 0; nt < 4; nt++) {
                    mma16816(acc[mt][nt], ah[mt], bh[nt]);
                }
            }
        }
    }

    // epilogue
#pragma unroll
    for (int mt = 0; mt < 2; mt++) {
        const int r0 = bm + warp_m + mt * 16 + (lane >> 2);
#pragma unroll
        for (int nt = 0; nt < 4; nt++) {
            const int col = bn + warp_n + nt * 8 + (lane & 3) * 2;
            const float b0 = bias[col], b1 = bias[col + 1];
            const float* c = acc[mt][nt];
            const size_t o0 = (size_t)r0 * N + col;
            const size_t o1 = (size_t)(r0 + 8) * N + col;
            float2 v0 = make_float2(c[0] + b0, c[1] + b1);
            float2 v1 = make_float2(c[2] + b0, c[3] + b1);
            if (add != nullptr) {
                const float2 a0 = *(const float2*)&add[o0];
                const float2 a1 = *(const float2*)&add[o1];
                v0.x += a0.x; v0.y += a0.y;
                v1.x += a1.x; v1.y += a1.y;
            }
            *(float2*)&C[o0] = v0;
            *(float2*)&C[o1] = v1;
        }
    }
}

// ---------------------------------------------------------------------------
// Flash-style causal attention with ALiBi (unchanged, fp32).
// ---------------------------------------------------------------------------
__global__ __launch_bounds__(256, 2)
void attn_kernel(const float* __restrict__ qkv, const float* __restrict__ alibi,
                 float* __restrict__ ctx)
{
    __shared__ float Ks[32][HDIM];
    __shared__ float Vs[32][HDIM];

    const int h   = blockIdx.y;
    const int qb  = blockIdx.x;
    const int tid = threadIdx.x;
    const int w    = tid >> 5;
    const int lane = tid & 31;
    const int qq = lane >> 2;
    const int g  = lane & 3;
    const int q  = qb * 64 + w * 8 + qq;

    const float* qrow = qkv + (size_t)q * QKV_N + h * 384 + g * 32;
    float qreg[32];
#pragma unroll
    for (int d = 0; d < 32; d += 4) {
        const float4 v4 = *(const float4*)(qrow + d);
        qreg[d + 0] = v4.x * INV_NORM;
        qreg[d + 1] = v4.y * INV_NORM;
        qreg[d + 2] = v4.z * INV_NORM;
        qreg[d + 3] = v4.w * INV_NORM;
    }

    float acc[32];
#pragma unroll
    for (int d = 0; d < 32; d++) acc[d] = 0.0f;
    float mrun = -INFINITY;
    float lrun = 0.0f;

    const float* alibi_h = alibi + (size_t)h * SEQ;
    const int kv_end = qb * 64 + 64;

    for (int kb = 0; kb < kv_end; kb += 32) {
        for (int i = tid; i < 32 * HDIM; i += 256) {
            const int r = i >> 7, c = i & 127;
            const float* base = qkv + (size_t)(kb + r) * QKV_N + h * 384;
            Ks[r][c] = base[128 + c];
            Vs[r][c] = base[256 + c];
        }
        __syncthreads();

#pragma unroll 1
        for (int jc = 0; jc < 32; jc += 8) {
            float s[8];
#pragma unroll
            for (int jj = 0; jj < 8; jj++) s[jj] = 0.0f;

#pragma unroll
            for (int d = 0; d < 32; d += 4) {
#pragma unroll
                for (int jj = 0; jj < 8; jj++) {
                    const float4 k4 = *(const float4*)&Ks[jc + jj][g * 32 + d];
                    s[jj] += qreg[d] * k4.x + qreg[d + 1] * k4.y
                           + qreg[d + 2] * k4.z + qreg[d + 3] * k4.w;
                }
            }
#pragma unroll
            for (int jj = 0; jj < 8; jj++) {
                s[jj] += __shfl_xor_sync(0xffffffffu, s[jj], 1);
                s[jj] += __shfl_xor_sync(0xffffffffu, s[jj], 2);
            }
            float mloc = -INFINITY;
#pragma unroll
            for (int jj = 0; jj < 8; jj++) {
                const int jg = kb + jc + jj;
                s[jj] = (jg <= q) ? (s[jj] + alibi_h[jg]) : -INFINITY;
                mloc = fmaxf(mloc, s[jj]);
            }
            if (mloc > mrun) {
                const float scale = __expf(mrun - mloc);
                mrun = mloc;
                lrun *= scale;
#pragma unroll
                for (int d = 0; d < 32; d++) acc[d] *= scale;
            }
#pragma unroll
            for (int jj = 0; jj < 8; jj++) {
                const float p = __expf(s[jj] - mrun);
                lrun += p;
#pragma unroll
                for (int d = 0; d < 32; d += 4) {
                    const float4 v4 = *(const float4*)&Vs[jc + jj][g * 32 + d];
                    acc[d + 0] += p * v4.x;
                    acc[d + 1] += p * v4.y;
                    acc[d + 2] += p * v4.z;
                    acc[d + 3] += p * v4.w;
                }
            }
        }
        __syncthreads();
    }

    const float inv_l = 1.0f / lrun;
    float* out = ctx + (size_t)q * HID + h * HDIM + g * 32;
#pragma unroll
    for (int d = 0; d < 32; d += 4) {
        float4 o = make_float4(acc[d] * inv_l, acc[d + 1] * inv_l,
                               acc[d + 2] * inv_l, acc[d + 3] * inv_l);
        *(float4*)(out + d) = o;
    }
}

// ---------------------------------------------------------------------------
// Launch
// inputs: 0 hidden_states, 1 residual, 2 alibi, 3 attention_mask (unused),
//         4 W_qkv [12288,4096], 5 b_qkv, 6 W_dense [4096,4096], 7 b_dense
// ---------------------------------------------------------------------------
extern "C" void kernel_launch(void* const* d_in, const int* in_sizes, int n_in,
                              void* d_out, int out_size)
{
    const float* hs       = (const float*)d_in[0];
    const float* residual = (const float*)d_in[1];
    const float* alibi    = (const float*)d_in[2];
    const float* Wqkv     = (const float*)d_in[4];
    const float* bqkv     = (const float*)d_in[5];
    const float* Wd       = (const float*)d_in[6];
    const float* bd       = (const float*)d_in[7];
    float* out = (float*)d_out;

    float *qkv_buf, *ctx_buf;
    __half *wq_h, *wd_h, *a_h;
    cudaGetSymbolAddress((void**)&qkv_buf, g_qkv);
    cudaGetSymbolAddress((void**)&ctx_buf, g_ctx);
    cudaGetSymbolAddress((void**)&wq_h, g_Wqkv_h);
    cudaGetSymbolAddress((void**)&wd_h, g_Wd_h);
    cudaGetSymbolAddress((void**)&a_h, g_A_h);

    cudaFuncSetAttribute(gemm_hmma, cudaFuncAttributeMaxDynamicSharedMemorySize, GSM_TOTAL);

    // 0) convert operands to fp16
    round16_kernel<<<2048, 256>>>(Wqkv, wq_h, QKV_N * HID);
    round16_kernel<<<2048, 256>>>(Wd, wd_h, HID * HID);
    round16_kernel<<<1024, 256>>>(hs, a_h, SEQ * HID);

    // 1) fused QKV projection: [2048,4096] @ [12288,4096]^T + b_qkv
    {
        dim3 grid(QKV_N / 128, SEQ / 128);
        gemm_hmma<<<grid, 512, GSM_TOTAL>>>(a_h, wq_h, bqkv, nullptr,
                                            qkv_buf, SEQ, QKV_N, HID);
    }
    // 2) attention
    {
        dim3 grid(SEQ / 64, NHEAD);
        attn_kernel<<<grid, 256>>>(qkv_buf, alibi, ctx_buf);
    }
    // 2b) round ctx to fp16 for dense GEMM
    round16_kernel<<<1024, 256>>>(ctx_buf, a_h, SEQ * HID);

    // 3) dense projection + bias + residual
    {
        dim3 grid(HID / 128, SEQ / 128);
        gemm_hmma<<<grid, 512, GSM_TOTAL>>>(a_h, wd_h, bd, residual,
                                            out, SEQ, HID, HID);
    }
}

// round 11
// speedup vs baseline: 9.1111x; 7.7146x over previous
#include <cuda_runtime.h>
#include <cuda_fp16.h>
#include <math.h>
#include <stdint.h>

// Problem constants (B=1)
#define SEQ   2048
#define HID   4096
#define NHEAD 32
#define HDIM  128
#define QKV_N 12288            // 3*HID
#define INV_NORM 0.08838834764831845f   // 1/sqrt(128)

// Scratch buffers (device globals; runtime alloc forbidden)
static __device__ __half g_qkv_h[(size_t)SEQ * QKV_N];
static __device__ __half g_Wqkv_h[(size_t)QKV_N * HID];
static __device__ __half g_Wd_h[(size_t)HID * HID];
static __device__ __half g_A_h[(size_t)SEQ * HID];   // hs fp16, later overwritten by ctx

// ---------------------------------------------------------------------------
// helpers
// ---------------------------------------------------------------------------
__device__ __forceinline__ uint32_t smem_u32(const void* p) {
    uint32_t a;
    asm("{ .reg .u64 t; cvta.to.shared.u64 t, %1; cvt.u32.u64 %0, t; }" : "=r"(a) : "l"(p));
    return a;
}
__device__ __forceinline__ void ldsm4(uint32_t* r, uint32_t addr) {
    asm volatile("ldmatrix.sync.aligned.m8n8.x4.shared.b16 {%0,%1,%2,%3}, [%4];"
                 : "=r"(r[0]), "=r"(r[1]), "=r"(r[2]), "=r"(r[3]) : "r"(addr));
}
__device__ __forceinline__ void ldsm4t(uint32_t* r, uint32_t addr) {
    asm volatile("ldmatrix.sync.aligned.m8n8.x4.trans.shared.b16 {%0,%1,%2,%3}, [%4];"
                 : "=r"(r[0]), "=r"(r[1]), "=r"(r[2]), "=r"(r[3]) : "r"(addr));
}
__device__ __forceinline__ void mma16816(float* c, const uint32_t* a, const uint32_t* b) {
    asm volatile(
        "mma.sync.aligned.m16n8k16.row.col.f32.f16.f16.f32 "
        "{%0,%1,%2,%3}, {%4,%5,%6,%7}, {%8,%9}, {%0,%1,%2,%3};"
        : "+f"(c[0]), "+f"(c[1]), "+f"(c[2]), "+f"(c[3])
        : "r"(a[0]), "r"(a[1]), "r"(a[2]), "r"(a[3]), "r"(b[0]), "r"(b[1]));
}
__device__ __forceinline__ void cp16(uint32_t dst, const void* src) {
    asm volatile("cp.async.cg.shared.global [%0], [%1], 16;" :: "r"(dst), "l"(src) : "memory");
}
__device__ __forceinline__ void cp_commit() {
    asm volatile("cp.async.commit_group;" ::: "memory");
}
template <int N>
__device__ __forceinline__ void cp_wait() {
    asm volatile("cp.async.wait_group %0;" :: "n"(N) : "memory");
}

// ---------------------------------------------------------------------------
// fp32 -> fp16 round (grid-stride, float4)
// ---------------------------------------------------------------------------
__global__ void round16_kernel(const float* __restrict__ x, __half* __restrict__ h, int n)
{
    const int stride = gridDim.x * blockDim.x * 4;
    for (int i = (blockIdx.x * blockDim.x + threadIdx.x) * 4; i < n; i += stride) {
        const float4 v = *(const float4*)(x + i);
        __half2 h0 = __floats2half2_rn(v.x, v.y);
        __half2 h1 = __floats2half2_rn(v.z, v.w);
        *(uint2*)(h + i) = make_uint2(*(uint32_t*)&h0, *(uint32_t*)&h1);
    }
}

// ---------------------------------------------------------------------------
// fp16 HMMA TN GEMM, cp.async 4-stage pipeline, 512 threads (16 warps).
// C[m,n] = sum_k A[m,k]*B[n,k] + bias[n] (+ add[m,n]); out fp32 or fp16.
// CTA tile 128x128, BK=32, warp grid 4m x 4n, warp tile 32x32.
// ---------------------------------------------------------------------------
#define SSTRIDE 40
#define STAGES 4
#define BK 32
#define BUF_BYTES (128 * SSTRIDE * 2)        // 10240
#define STAGE_BYTES (2 * BUF_BYTES)          // 20480
#define GSM_TOTAL (STAGES * STAGE_BYTES)     // 81920

template <bool HALF_OUT>
__global__ __launch_bounds__(512, 1)
void gemm_hmma(const __half* __restrict__ Ag, const __half* __restrict__ Bg,
               const float* __restrict__ bias, const float* __restrict__ add,
               void* __restrict__ Cv, int M, int N, int K)
{
    extern __shared__ char smem[];
    const uint32_t sb = smem_u32(smem);

    const int tid  = threadIdx.x;
    const int wid  = tid >> 5;
    const int lane = tid & 31;
    const int bm = blockIdx.y * 128;
    const int bn = blockIdx.x * 128;

    const int warp_m = (wid & 3) * 32;
    const int warp_n = (wid >> 2) * 32;

    const int lrow = tid >> 2;
    const int lcol = (tid & 3) * 8;
    const __half* gA = Ag + (size_t)(bm + lrow) * K + lcol;
    const __half* gB = Bg + (size_t)(bn + lrow) * K + lcol;
    const uint32_t sdst = (uint32_t)(lrow * SSTRIDE + lcol) * 2;

    const int a_r = warp_m + (lane & 15);
    const int a_c = (lane >> 4) * 8;
    const int b_r = warp_n + (lane >> 4) * 8 + (lane & 7);
    const int b_c = ((lane >> 3) & 1) * 8;

    float acc[2][4][4];
#pragma unroll
    for (int i = 0; i < 2; i++)
#pragma unroll
        for (int j = 0; j < 4; j++)
#pragma unroll
            for (int e = 0; e < 4; e++) acc[i][j][e] = 0.0f;

    const int NCH = K >> 5;

    auto issue = [&](int ch) {
        const uint32_t base = sb + (uint32_t)(ch % STAGES) * STAGE_BYTES;
        const int ko = ch * BK;
        cp16(base + sdst,             gA + ko);
        cp16(base + BUF_BYTES + sdst, gB + ko);
        cp_commit();
    };

#pragma unroll
    for (int ch = 0; ch < STAGES - 1; ch++) issue(ch);

    for (int ch = 0; ch < NCH; ch++) {
        cp_wait<STAGES - 2>();
        __syncthreads();
        if (ch + STAGES - 1 < NCH) issue(ch + STAGES - 1);

        const uint32_t base = sb + (uint32_t)(ch % STAGES) * STAGE_BYTES;
        const uint32_t aA = base;
        const uint32_t aB = base + BUF_BYTES;

#pragma unroll
        for (int ks = 0; ks < 2; ks++) {
            const int kc = ks * 16;
            uint32_t ah[2][4], bh[4][2];
#pragma unroll
            for (int mt = 0; mt < 2; mt++) {
                const uint32_t off = (uint32_t)(((a_r + mt * 16) * SSTRIDE + kc + a_c) * 2);
                ldsm4(ah[mt], aA + off);
            }
#pragma unroll
            for (int ntp = 0; ntp < 2; ntp++) {
                const uint32_t off = (uint32_t)(((b_r + ntp * 16) * SSTRIDE + kc + b_c) * 2);
                uint32_t r[4];
                ldsm4(r, aB + off);
                bh[ntp * 2][0] = r[0]; bh[ntp * 2][1] = r[1];
                bh[ntp * 2 + 1][0] = r[2]; bh[ntp * 2 + 1][1] = r[3];
            }
#pragma unroll
            for (int mt = 0; mt < 2; mt++)
#pragma unroll
                for (int nt = 0; nt < 4; nt++)
                    mma16816(acc[mt][nt], ah[mt], bh[nt]);
        }
    }

    // epilogue
#pragma unroll
    for (int mt = 0; mt < 2; mt++) {
        const int r0 = bm + warp_m + mt * 16 + (lane >> 2);
#pragma unroll
        for (int nt = 0; nt < 4; nt++) {
            const int col = bn + warp_n + nt * 8 + (lane & 3) * 2;
            const float b0 = bias[col], b1 = bias[col + 1];
            const float* c = acc[mt][nt];
            const size_t o0 = (size_t)r0 * N + col;
            const size_t o1 = (size_t)(r0 + 8) * N + col;
            float2 v0 = make_float2(c[0] + b0, c[1] + b1);
            float2 v1 = make_float2(c[2] + b0, c[3] + b1);
            if (add != nullptr) {
                const float2 a0 = *(const float2*)&add[o0];
                const float2 a1 = *(const float2*)&add[o1];
                v0.x += a0.x; v0.y += a0.y;
                v1.x += a1.x; v1.y += a1.y;
            }
            if (HALF_OUT) {
                __half* C = (__half*)Cv;
                *(__half2*)&C[o0] = __floats2half2_rn(v0.x, v0.y);
                *(__half2*)&C[o1] = __floats2half2_rn(v1.x, v1.y);
            } else {
                float* C = (float*)Cv;
                *(float2*)&C[o0] = v0;
                *(float2*)&C[o1] = v1;
            }
        }
    }
}

// ---------------------------------------------------------------------------
// Tensor-core flash attention with ALiBi (fp16 inputs, fp32 softmax/accum).
// grid = (SEQ/64, NHEAD), 128 threads (4 warps); warp owns 16 q rows.
// Q kept in registers as MMA A-frags. K/V 64-row tiles double-buffered cp.async.
// QK: K tile [kv][d] is n-major/k-contig -> non-trans ldmatrix (validated).
// PV: V tile [j][d] is k-major/n-contig -> ldmatrix.trans for B-frags.
// ctx written fp16 directly.
// ---------------------------------------------------------------------------
#define VSTRIDE 136                       // halves per smem row (272B, conflict-free)
#define KTILE_B (64 * VSTRIDE * 2)        // 17408
#define STAGE_A (2 * KTILE_B + 256)       // K, V, alibi(64 f32) = 35072
#define ATT_SMEM (2 * STAGE_A)            // 70144

__global__ __launch_bounds__(128, 1)
void attn_hmma(const __half* __restrict__ qkv, const float* __restrict__ alibi,
               __half* __restrict__ ctx)
{
    extern __shared__ char smem[];
    const uint32_t sb = smem_u32(smem);
    const int h = blockIdx.y, qb = blockIdx.x;
    const int tid = threadIdx.x, wid = tid >> 5, lane = tid & 31;
    const int qw0 = qb * 64 + wid * 16;   // warp's first q row
    const int r0 = lane >> 2;             // 0..7
    const int c0 = (lane & 3) * 2;

    // Q fragments: 8 ksteps x 4 regs (held for the whole kernel)
    uint32_t qf[8][4];
    {
        const __half* qbase = qkv + (size_t)qw0 * QKV_N + h * 384;
#pragma unroll
        for (int ks = 0; ks < 8; ks++) {
            const int col = ks * 16 + c0;
            qf[ks][0] = *(const uint32_t*)(qbase + (size_t)r0 * QKV_N + col);
            qf[ks][1] = *(const uint32_t*)(qbase + (size_t)(r0 + 8) * QKV_N + col);
            qf[ks][2] = *(const uint32_t*)(qbase + (size_t)r0 * QKV_N + col + 8);
            qf[ks][3] = *(const uint32_t*)(qbase + (size_t)(r0 + 8) * QKV_N + col + 8);
        }
    }

    float oacc[16][4];
#pragma unroll
    for (int i = 0; i < 16; i++)
#pragma unroll
        for (int e = 0; e < 4; e++) oacc[i][e] = 0.0f;
    float mr0 = -INFINITY, mr1 = -INFINITY, ls0 = 0.0f, ls1 = 0.0f;

    const int nt = qb + 1;

    auto issue = [&](int t) {
        const uint32_t base = sb + (uint32_t)(t & 1) * STAGE_A;
        const int kv0 = t * 64;
        const int r = tid >> 1, chl = tid & 1;
        const __half* ksrc = qkv + (size_t)(kv0 + r) * QKV_N + h * 384 + 128 + chl * 64;
        const uint32_t kdst = base + (uint32_t)(r * VSTRIDE + chl * 64) * 2;
#pragma unroll
        for (int c = 0; c < 8; c++) {
            cp16(kdst + c * 16,           ksrc + c * 8);
            cp16(kdst + KTILE_B + c * 16, ksrc + 128 + c * 8);   // V
        }
        if (tid < 16)
            cp16(base + 2 * KTILE_B + tid * 16,
                 alibi + (size_t)h * SEQ + kv0 + tid * 4);
        cp_commit();
    };

    issue(0);

    for (int t = 0; t < nt; t++) {
        cp_wait<0>();
        __syncthreads();
        if (t + 1 < nt) issue(t + 1);

        const uint32_t base = sb + (uint32_t)(t & 1) * STAGE_A;
        const uint32_t Ks = base, Vs = base + KTILE_B;
        const float* albuf = (const float*)(smem + (size_t)(t & 1) * STAGE_A + 2 * KTILE_B);

        // ---- S = Q @ K^T ----
        float sacc[8][4];
#pragma unroll
        for (int i = 0; i < 8; i++)
#pragma unroll
            for (int e = 0; e < 4; e++) sacc[i][e] = 0.0f;

#pragma unroll
        for (int ks = 0; ks < 8; ks++) {
            const int kc = ks * 16;
#pragma unroll
            for (int ntp = 0; ntp < 4; ntp++) {
                uint32_t rr[4];
                const uint32_t addr = Ks +
                    (uint32_t)(((ntp * 16 + (lane >> 4) * 8 + (lane & 7)) * VSTRIDE
                                + kc + ((lane >> 3) & 1) * 8) * 2);
                ldsm4(rr, addr);
                uint32_t b0[2] = {rr[0], rr[1]}, b1[2] = {rr[2], rr[3]};
                mma16816(sacc[2 * ntp],     qf[ks], b0);
                mma16816(sacc[2 * ntp + 1], qf[ks], b1);
            }
        }

        // ---- softmax (fp32) ----
        const int kv0 = t * 64;
        const int qg0 = qw0 + r0, qg1 = qg0 + 8;
        float m0 = -INFINITY, m1 = -INFINITY;
#pragma unroll
        for (int n8 = 0; n8 < 8; n8++) {
            const int j0 = n8 * 8 + c0;
            const float a0 = albuf[j0], a1 = albuf[j0 + 1];
            const int jg0 = kv0 + j0;
            float v0 = sacc[n8][0] * INV_NORM + a0;
            float v1 = sacc[n8][1] * INV_NORM + a1;
            float v2 = sacc[n8][2] * INV_NORM + a0;
            float v3 = sacc[n8][3] * INV_NORM + a1;
            if (jg0     > qg0) v0 = -INFINITY;
            if (jg0 + 1 > qg0) v1 = -INFINITY;
            if (jg0     > qg1) v2 = -INFINITY;
            if (jg0 + 1 > qg1) v3 = -INFINITY;
            sacc[n8][0] = v0; sacc[n8][1] = v1; sacc[n8][2] = v2; sacc[n8][3] = v3;
            m0 = fmaxf(m0, fmaxf(v0, v1));
            m1 = fmaxf(m1, fmaxf(v2, v3));
        }
        m0 = fmaxf(m0, __shfl_xor_sync(0xffffffffu, m0, 1));
        m0 = fmaxf(m0, __shfl_xor_sync(0xffffffffu, m0, 2));
        m1 = fmaxf(m1, __shfl_xor_sync(0xffffffffu, m1, 1));
        m1 = fmaxf(m1, __shfl_xor_sync(0xffffffffu, m1, 2));
        const float nm0 = fmaxf(mr0, m0), nm1 = fmaxf(mr1, m1);
        const float f0 = __expf(mr0 - nm0), f1 = __expf(mr1 - nm1);
        mr0 = nm0; mr1 = nm1;
        ls0 *= f0; ls1 *= f1;
#pragma unroll
        for (int i = 0; i < 16; i++) {
            oacc[i][0] *= f0; oacc[i][1] *= f0;
            oacc[i][2] *= f1; oacc[i][3] *= f1;
        }

        // P -> fp16 A-frags (register-only; C-frag -> A-frag identity)
        uint32_t pf[4][4];
#pragma unroll
        for (int n8 = 0; n8 < 8; n8++) {
            const float p0 = __expf(sacc[n8][0] - nm0);
            const float p1 = __expf(sacc[n8][1] - nm0);
            const float p2 = __expf(sacc[n8][2] - nm1);
            const float p3 = __expf(sacc[n8][3] - nm1);
            ls0 += p0 + p1; ls1 += p2 + p3;
            __half2 h01 = __floats2half2_rn(p0, p1);
            __half2 h23 = __floats2half2_rn(p2, p3);
            const int ks = n8 >> 1, hi = n8 & 1;
            pf[ks][2 * hi]     = *(uint32_t*)&h01;   // a0 / a2
            pf[ks][2 * hi + 1] = *(uint32_t*)&h23;   // a1 / a3
        }

        // ---- O += P @ V  (V transposed via ldmatrix.trans) ----
#pragma unroll
        for (int ks = 0; ks < 4; ks++) {
#pragma unroll
            for (int g = 0; g < 8; g++) {
                uint32_t rr[4];
                const uint32_t addr = Vs +
                    (uint32_t)(((ks * 16 + ((lane >> 3) & 1) * 8 + (lane & 7)) * VSTRIDE
                                + g * 16 + (lane >> 4) * 8) * 2);
                ldsm4t(rr, addr);
                uint32_t b0[2] = {rr[0], rr[1]}, b1[2] = {rr[2], rr[3]};
                mma16816(oacc[2 * g],     pf[ks], b0);
                mma16816(oacc[2 * g + 1], pf[ks], b1);
            }
        }
    }

    // ---- finalize ----
    ls0 += __shfl_xor_sync(0xffffffffu, ls0, 1);
    ls0 += __shfl_xor_sync(0xffffffffu, ls0, 2);
    ls1 += __shfl_xor_sync(0xffffffffu, ls1, 1);
    ls1 += __shfl_xor_sync(0xffffffffu, ls1, 2);
    const float inv0 = 1.0f / ls0, inv1 = 1.0f / ls1;

    __half* out0 = ctx + (size_t)(qw0 + r0) * HID + h * HDIM;
    __half* out1 = out0 + (size_t)8 * HID;
#pragma unroll
    for (int nd = 0; nd < 16; nd++) {
        const int d = nd * 8 + c0;
        *(__half2*)(out0 + d) = __floats2half2_rn(oacc[nd][0] * inv0, oacc[nd][1] * inv0);
        *(__half2*)(out1 + d) = __floats2half2_rn(oacc[nd][2] * inv1, oacc[nd][3] * inv1);
    }
}

// ---------------------------------------------------------------------------
// Launch
// inputs: 0 hidden_states, 1 residual, 2 alibi, 3 attention_mask (unused),
//         4 W_qkv [12288,4096], 5 b_qkv, 6 W_dense [4096,4096], 7 b_dense
// ---------------------------------------------------------------------------
extern "C" void kernel_launch(void* const* d_in, const int* in_sizes, int n_in,
                              void* d_out, int out_size)
{
    const float* hs       = (const float*)d_in[0];
    const float* residual = (const float*)d_in[1];
    const float* alibi    = (const float*)d_in[2];
    const float* Wqkv     = (const float*)d_in[4];
    const float* bqkv     = (const float*)d_in[5];
    const float* Wd       = (const float*)d_in[6];
    const float* bd       = (const float*)d_in[7];
    float* out = (float*)d_out;

    __half *qkv_h, *wq_h, *wd_h, *a_h;
    cudaGetSymbolAddress((void**)&qkv_h, g_qkv_h);
    cudaGetSymbolAddress((void**)&wq_h, g_Wqkv_h);
    cudaGetSymbolAddress((void**)&wd_h, g_Wd_h);
    cudaGetSymbolAddress((void**)&a_h, g_A_h);

    cudaFuncSetAttribute(gemm_hmma<true>,  cudaFuncAttributeMaxDynamicSharedMemorySize, GSM_TOTAL);
    cudaFuncSetAttribute(gemm_hmma<false>, cudaFuncAttributeMaxDynamicSharedMemorySize, GSM_TOTAL);
    cudaFuncSetAttribute(attn_hmma, cudaFuncAttributeMaxDynamicSharedMemorySize, ATT_SMEM);

    // 0) convert operands to fp16
    round16_kernel<<<2048, 256>>>(Wqkv, wq_h, QKV_N * HID);
    round16_kernel<<<2048, 256>>>(Wd, wd_h, HID * HID);
    round16_kernel<<<1024, 256>>>(hs, a_h, SEQ * HID);

    // 1) fused QKV projection -> fp16 qkv
    {
        dim3 grid(QKV_N / 128, SEQ / 128);
        gemm_hmma<true><<<grid, 512, GSM_TOTAL>>>(a_h, wq_h, bqkv, nullptr,
                                                  qkv_h, SEQ, QKV_N, HID);
    }
    // 2) tensor-core flash attention -> ctx fp16 (overwrites a_h; hs no longer needed)
    {
        dim3 grid(SEQ / 64, NHEAD);
        attn_hmma<<<grid, 128, ATT_SMEM>>>(qkv_h, alibi, a_h);
    }
    // 3) dense projection + bias + residual -> fp32 out
    {
        dim3 grid(HID / 128, SEQ / 128);
        gemm_hmma<false><<<grid, 512, GSM_TOTAL>>>(a_h, wd_h, bd, residual,
                                                   out, SEQ, HID, HID);
    }
}

// round 12
// speedup vs baseline: 9.2585x; 1.0162x over previous
#include <cuda_runtime.h>
#include <cuda_fp16.h>
#include <math.h>
#include <stdint.h>

// Problem constants (B=1)
#define SEQ   2048
#define HID   4096
#define NHEAD 32
#define HDIM  128
#define QKV_N 12288            // 3*HID
#define INV_NORM 0.08838834764831845f   // 1/sqrt(128)

// Scratch buffers (device globals; runtime alloc forbidden)
static __device__ __half g_qkv_h[(size_t)SEQ * QKV_N];
static __device__ __half g_Wqkv_h[(size_t)QKV_N * HID];
static __device__ __half g_Wd_h[(size_t)HID * HID];
static __device__ __half g_A_h[(size_t)SEQ * HID];   // hs fp16, later overwritten by ctx

// ---------------------------------------------------------------------------
// helpers
// ---------------------------------------------------------------------------
__device__ __forceinline__ uint32_t smem_u32(const void* p) {
    uint32_t a;
    asm("{ .reg .u64 t; cvta.to.shared.u64 t, %1; cvt.u32.u64 %0, t; }" : "=r"(a) : "l"(p));
    return a;
}
__device__ __forceinline__ void ldsm4(uint32_t* r, uint32_t addr) {
    asm volatile("ldmatrix.sync.aligned.m8n8.x4.shared.b16 {%0,%1,%2,%3}, [%4];"
                 : "=r"(r[0]), "=r"(r[1]), "=r"(r[2]), "=r"(r[3]) : "r"(addr));
}
__device__ __forceinline__ void ldsm4t(uint32_t* r, uint32_t addr) {
    asm volatile("ldmatrix.sync.aligned.m8n8.x4.trans.shared.b16 {%0,%1,%2,%3}, [%4];"
                 : "=r"(r[0]), "=r"(r[1]), "=r"(r[2]), "=r"(r[3]) : "r"(addr));
}
__device__ __forceinline__ void mma16816(float* c, const uint32_t* a, const uint32_t* b) {
    asm volatile(
        "mma.sync.aligned.m16n8k16.row.col.f32.f16.f16.f32 "
        "{%0,%1,%2,%3}, {%4,%5,%6,%7}, {%8,%9}, {%0,%1,%2,%3};"
        : "+f"(c[0]), "+f"(c[1]), "+f"(c[2]), "+f"(c[3])
        : "r"(a[0]), "r"(a[1]), "r"(a[2]), "r"(a[3]), "r"(b[0]), "r"(b[1]));
}
__device__ __forceinline__ void cp16(uint32_t dst, const void* src) {
    asm volatile("cp.async.cg.shared.global [%0], [%1], 16;" :: "r"(dst), "l"(src) : "memory");
}
__device__ __forceinline__ void cp_commit() {
    asm volatile("cp.async.commit_group;" ::: "memory");
}
template <int N>
__device__ __forceinline__ void cp_wait() {
    asm volatile("cp.async.wait_group %0;" :: "n"(N) : "memory");
}

// ---------------------------------------------------------------------------
// fp32 -> fp16 round (grid-stride, float4)
// ---------------------------------------------------------------------------
__global__ void round16_kernel(const float* __restrict__ x, __half* __restrict__ h, int n)
{
    const int stride = gridDim.x * blockDim.x * 4;
    for (int i = (blockIdx.x * blockDim.x + threadIdx.x) * 4; i < n; i += stride) {
        const float4 v = *(const float4*)(x + i);
        __half2 h0 = __floats2half2_rn(v.x, v.y);
        __half2 h1 = __floats2half2_rn(v.z, v.w);
        *(uint2*)(h + i) = make_uint2(*(uint32_t*)&h0, *(uint32_t*)&h1);
    }
}

// ---------------------------------------------------------------------------
// fp16 HMMA TN GEMM, cp.async 4-stage pipeline, 256 threads (8 warps),
// 2 CTAs/SM (independent barrier domains).
// C[m,n] = sum_k A[m,k]*B[n,k] + bias[n] (+ add[m,n]); out fp32 or fp16.
// CTA tile 128x128, BK=32, warp grid 4m x 2n, warp tile 32x64.
// ---------------------------------------------------------------------------
#define SSTRIDE 40
#define STAGES 4
#define BK 32
#define BUF_BYTES (128 * SSTRIDE * 2)        // 10240
#define STAGE_BYTES (2 * BUF_BYTES)          // 20480
#define GSM_TOTAL (STAGES * STAGE_BYTES)     // 81920

template <bool HALF_OUT>
__global__ __launch_bounds__(256, 2)
void gemm_hmma(const __half* __restrict__ Ag, const __half* __restrict__ Bg,
               const float* __restrict__ bias, const float* __restrict__ add,
               void* __restrict__ Cv, int M, int N, int K)
{
    extern __shared__ char smem[];
    const uint32_t sb = smem_u32(smem);

    const int tid  = threadIdx.x;
    const int wid  = tid >> 5;
    const int lane = tid & 31;
    const int bm = blockIdx.y * 128;
    const int bn = blockIdx.x * 128;

    const int warp_m = (wid & 3) * 32;     // 4 warps along M
    const int warp_n = (wid >> 2) * 64;    // 2 warps along N (tile 32x64)

    // loader mapping: thread -> row (0..127), 16-col half
    const int lrow = tid >> 1;
    const int lcol = (tid & 1) * 16;
    const __half* gA = Ag + (size_t)(bm + lrow) * K + lcol;
    const __half* gB = Bg + (size_t)(bn + lrow) * K + lcol;
    const uint32_t sdst = (uint32_t)(lrow * SSTRIDE + lcol) * 2;

    const int a_r = warp_m + (lane & 15);
    const int a_c = (lane >> 4) * 8;
    const int b_rr = (lane >> 4) * 8 + (lane & 7);
    const int b_c = ((lane >> 3) & 1) * 8;

    float acc[2][8][4];
#pragma unroll
    for (int i = 0; i < 2; i++)
#pragma unroll
        for (int j = 0; j < 8; j++)
#pragma unroll
            for (int e = 0; e < 4; e++) acc[i][j][e] = 0.0f;

    const int NCH = K >> 5;

    auto issue = [&](int ch) {
        const uint32_t base = sb + (uint32_t)(ch % STAGES) * STAGE_BYTES;
        const int ko = ch * BK;
        cp16(base + sdst,                  gA + ko);
        cp16(base + sdst + 16,             gA + ko + 8);
        cp16(base + BUF_BYTES + sdst,      gB + ko);
        cp16(base + BUF_BYTES + sdst + 16, gB + ko + 8);
        cp_commit();
    };

#pragma unroll
    for (int ch = 0; ch < STAGES - 1; ch++) issue(ch);

    for (int ch = 0; ch < NCH; ch++) {
        cp_wait<STAGES - 2>();
        __syncthreads();
        if (ch + STAGES - 1 < NCH) issue(ch + STAGES - 1);

        const uint32_t base = sb + (uint32_t)(ch % STAGES) * STAGE_BYTES;
        const uint32_t aA = base;
        const uint32_t aB = base + BUF_BYTES;

#pragma unroll
        for (int ks = 0; ks < 2; ks++) {
            const int kc = ks * 16;
            uint32_t ah[2][4], bh[8][2];
#pragma unroll
            for (int mt = 0; mt < 2; mt++) {
                const uint32_t off = (uint32_t)(((a_r + mt * 16) * SSTRIDE + kc + a_c) * 2);
                ldsm4(ah[mt], aA + off);
            }
#pragma unroll
            for (int ntp = 0; ntp < 4; ntp++) {
                const uint32_t off = (uint32_t)(((warp_n + ntp * 16 + b_rr) * SSTRIDE
                                                 + kc + b_c) * 2);
                uint32_t r[4];
                ldsm4(r, aB + off);
                bh[ntp * 2][0] = r[0]; bh[ntp * 2][1] = r[1];
                bh[ntp * 2 + 1][0] = r[2]; bh[ntp * 2 + 1][1] = r[3];
            }
#pragma unroll
            for (int mt = 0; mt < 2; mt++)
#pragma unroll
                for (int nt = 0; nt < 8; nt++)
                    mma16816(acc[mt][nt], ah[mt], bh[nt]);
        }
    }

    // epilogue
#pragma unroll
    for (int mt = 0; mt < 2; mt++) {
        const int r0 = bm + warp_m + mt * 16 + (lane >> 2);
#pragma unroll
        for (int nt = 0; nt < 8; nt++) {
            const int col = bn + warp_n + nt * 8 + (lane & 3) * 2;
            const float b0 = bias[col], b1 = bias[col + 1];
            const float* c = acc[mt][nt];
            const size_t o0 = (size_t)r0 * N + col;
            const size_t o1 = (size_t)(r0 + 8) * N + col;
            float2 v0 = make_float2(c[0] + b0, c[1] + b1);
            float2 v1 = make_float2(c[2] + b0, c[3] + b1);
            if (add != nullptr) {
                const float2 a0 = *(const float2*)&add[o0];
                const float2 a1 = *(const float2*)&add[o1];
                v0.x += a0.x; v0.y += a0.y;
                v1.x += a1.x; v1.y += a1.y;
            }
            if (HALF_OUT) {
                __half* C = (__half*)Cv;
                *(__half2*)&C[o0] = __floats2half2_rn(v0.x, v0.y);
                *(__half2*)&C[o1] = __floats2half2_rn(v1.x, v1.y);
            } else {
                float* C = (float*)Cv;
                *(float2*)&C[o0] = v0;
                *(float2*)&C[o1] = v1;
            }
        }
    }
}

// ---------------------------------------------------------------------------
// Tensor-core flash attention with ALiBi (fp16 inputs, fp32 softmax/accum).
// (unchanged from R11 — passed at rel_err 4.1e-4)
// ---------------------------------------------------------------------------
#define VSTRIDE 136
#define KTILE_B (64 * VSTRIDE * 2)
#define STAGE_A (2 * KTILE_B + 256)
#define ATT_SMEM (2 * STAGE_A)

__global__ __launch_bounds__(128, 1)
void attn_hmma(const __half* __restrict__ qkv, const float* __restrict__ alibi,
               __half* __restrict__ ctx)
{
    extern __shared__ char smem[];
    const uint32_t sb = smem_u32(smem);
    const int h = blockIdx.y, qb = blockIdx.x;
    const int tid = threadIdx.x, wid = tid >> 5, lane = tid & 31;
    const int qw0 = qb * 64 + wid * 16;
    const int r0 = lane >> 2;
    const int c0 = (lane & 3) * 2;

    uint32_t qf[8][4];
    {
        const __half* qbase = qkv + (size_t)qw0 * QKV_N + h * 384;
#pragma unroll
        for (int ks = 0; ks < 8; ks++) {
            const int col = ks * 16 + c0;
            qf[ks][0] = *(const uint32_t*)(qbase + (size_t)r0 * QKV_N + col);
            qf[ks][1] = *(const uint32_t*)(qbase + (size_t)(r0 + 8) * QKV_N + col);
            qf[ks][2] = *(const uint32_t*)(qbase + (size_t)r0 * QKV_N + col + 8);
            qf[ks][3] = *(const uint32_t*)(qbase + (size_t)(r0 + 8) * QKV_N + col + 8);
        }
    }

    float oacc[16][4];
#pragma unroll
    for (int i = 0; i < 16; i++)
#pragma unroll
        for (int e = 0; e < 4; e++) oacc[i][e] = 0.0f;
    float mr0 = -INFINITY, mr1 = -INFINITY, ls0 = 0.0f, ls1 = 0.0f;

    const int nt = qb + 1;

    auto issue = [&](int t) {
        const uint32_t base = sb + (uint32_t)(t & 1) * STAGE_A;
        const int kv0 = t * 64;
        const int r = tid >> 1, chl = tid & 1;
        const __half* ksrc = qkv + (size_t)(kv0 + r) * QKV_N + h * 384 + 128 + chl * 64;
        const uint32_t kdst = base + (uint32_t)(r * VSTRIDE + chl * 64) * 2;
#pragma unroll
        for (int c = 0; c < 8; c++) {
            cp16(kdst + c * 16,           ksrc + c * 8);
            cp16(kdst + KTILE_B + c * 16, ksrc + 128 + c * 8);
        }
        if (tid < 16)
            cp16(base + 2 * KTILE_B + tid * 16,
                 alibi + (size_t)h * SEQ + kv0 + tid * 4);
        cp_commit();
    };

    issue(0);

    for (int t = 0; t < nt; t++) {
        cp_wait<0>();
        __syncthreads();
        if (t + 1 < nt) issue(t + 1);

        const uint32_t base = sb + (uint32_t)(t & 1) * STAGE_A;
        const uint32_t Ks = base, Vs = base + KTILE_B;
        const float* albuf = (const float*)(smem + (size_t)(t & 1) * STAGE_A + 2 * KTILE_B);

        float sacc[8][4];
#pragma unroll
        for (int i = 0; i < 8; i++)
#pragma unroll
            for (int e = 0; e < 4; e++) sacc[i][e] = 0.0f;

#pragma unroll
        for (int ks = 0; ks < 8; ks++) {
            const int kc = ks * 16;
#pragma unroll
            for (int ntp = 0; ntp < 4; ntp++) {
                uint32_t rr[4];
                const uint32_t addr = Ks +
                    (uint32_t)(((ntp * 16 + (lane >> 4) * 8 + (lane & 7)) * VSTRIDE
                                + kc + ((lane >> 3) & 1) * 8) * 2);
                ldsm4(rr, addr);
                uint32_t b0[2] = {rr[0], rr[1]}, b1[2] = {rr[2], rr[3]};
                mma16816(sacc[2 * ntp],     qf[ks], b0);
                mma16816(sacc[2 * ntp + 1], qf[ks], b1);
            }
        }

        const int kv0 = t * 64;
        const int qg0 = qw0 + r0, qg1 = qg0 + 8;
        float m0 = -INFINITY, m1 = -INFINITY;
#pragma unroll
        for (int n8 = 0; n8 < 8; n8++) {
            const int j0 = n8 * 8 + c0;
            const float a0 = albuf[j0], a1 = albuf[j0 + 1];
            const int jg0 = kv0 + j0;
            float v0 = sacc[n8][0] * INV_NORM + a0;
            float v1 = sacc[n8][1] * INV_NORM + a1;
            float v2 = sacc[n8][2] * INV_NORM + a0;
            float v3 = sacc[n8][3] * INV_NORM + a1;
            if (jg0     > qg0) v0 = -INFINITY;
            if (jg0 + 1 > qg0) v1 = -INFINITY;
            if (jg0     > qg1) v2 = -INFINITY;
            if (jg0 + 1 > qg1) v3 = -INFINITY;
            sacc[n8][0] = v0; sacc[n8][1] = v1; sacc[n8][2] = v2; sacc[n8][3] = v3;
            m0 = fmaxf(m0, fmaxf(v0, v1));
            m1 = fmaxf(m1, fmaxf(v2, v3));
        }
        m0 = fmaxf(m0, __shfl_xor_sync(0xffffffffu, m0, 1));
        m0 = fmaxf(m0, __shfl_xor_sync(0xffffffffu, m0, 2));
        m1 = fmaxf(m1, __shfl_xor_sync(0xffffffffu, m1, 1));
        m1 = fmaxf(m1, __shfl_xor_sync(0xffffffffu, m1, 2));
        const float nm0 = fmaxf(mr0, m0), nm1 = fmaxf(mr1, m1);
        const float f0 = __expf(mr0 - nm0), f1 = __expf(mr1 - nm1);
        mr0 = nm0; mr1 = nm1;
        ls0 *= f0; ls1 *= f1;
#pragma unroll
        for (int i = 0; i < 16; i++) {
            oacc[i][0] *= f0; oacc[i][1] *= f0;
            oacc[i][2] *= f1; oacc[i][3] *= f1;
        }

        uint32_t pf[4][4];
#pragma unroll
        for (int n8 = 0; n8 < 8; n8++) {
            const float p0 = __expf(sacc[n8][0] - nm0);
            const float p1 = __expf(sacc[n8][1] - nm0);
            const float p2 = __expf(sacc[n8][2] - nm1);
            const float p3 = __expf(sacc[n8][3] - nm1);
            ls0 += p0 + p1; ls1 += p2 + p3;
            __half2 h01 = __floats2half2_rn(p0, p1);
            __half2 h23 = __floats2half2_rn(p2, p3);
            const int ks = n8 >> 1, hi = n8 & 1;
            pf[ks][2 * hi]     = *(uint32_t*)&h01;
            pf[ks][2 * hi + 1] = *(uint32_t*)&h23;
        }

#pragma unroll
        for (int ks = 0; ks < 4; ks++) {
#pragma unroll
            for (int g = 0; g < 8; g++) {
                uint32_t rr[4];
                const uint32_t addr = Vs +
                    (uint32_t)(((ks * 16 + ((lane >> 3) & 1) * 8 + (lane & 7)) * VSTRIDE
                                + g * 16 + (lane >> 4) * 8) * 2);
                ldsm4t(rr, addr);
                uint32_t b0[2] = {rr[0], rr[1]}, b1[2] = {rr[2], rr[3]};
                mma16816(oacc[2 * g],     pf[ks], b0);
                mma16816(oacc[2 * g + 1], pf[ks], b1);
            }
        }
    }

    ls0 += __shfl_xor_sync(0xffffffffu, ls0, 1);
    ls0 += __shfl_xor_sync(0xffffffffu, ls0, 2);
    ls1 += __shfl_xor_sync(0xffffffffu, ls1, 1);
    ls1 += __shfl_xor_sync(0xffffffffu, ls1, 2);
    const float inv0 = 1.0f / ls0, inv1 = 1.0f / ls1;

    __half* out0 = ctx + (size_t)(qw0 + r0) * HID + h * HDIM;
    __half* out1 = out0 + (size_t)8 * HID;
#pragma unroll
    for (int nd = 0; nd < 16; nd++) {
        const int d = nd * 8 + c0;
        *(__half2*)(out0 + d) = __floats2half2_rn(oacc[nd][0] * inv0, oacc[nd][1] * inv0);
        *(__half2*)(out1 + d) = __floats2half2_rn(oacc[nd][2] * inv1, oacc[nd][3] * inv1);
    }
}

// ---------------------------------------------------------------------------
// Launch
// inputs: 0 hidden_states, 1 residual, 2 alibi, 3 attention_mask (unused),
//         4 W_qkv [12288,4096], 5 b_qkv, 6 W_dense [4096,4096], 7 b_dense
// ---------------------------------------------------------------------------
extern "C" void kernel_launch(void* const* d_in, const int* in_sizes, int n_in,
                              void* d_out, int out_size)
{
    const float* hs       = (const float*)d_in[0];
    const float* residual = (const float*)d_in[1];
    const float* alibi    = (const float*)d_in[2];
    const float* Wqkv     = (const float*)d_in[4];
    const float* bqkv     = (const float*)d_in[5];
    const float* Wd       = (const float*)d_in[6];
    const float* bd       = (const float*)d_in[7];
    float* out = (float*)d_out;

    __half *qkv_h, *wq_h, *wd_h, *a_h;
    cudaGetSymbolAddress((void**)&qkv_h, g_qkv_h);
    cudaGetSymbolAddress((void**)&wq_h, g_Wqkv_h);
    cudaGetSymbolAddress((void**)&wd_h, g_Wd_h);
    cudaGetSymbolAddress((void**)&a_h, g_A_h);

    cudaFuncSetAttribute(gemm_hmma<true>,  cudaFuncAttributeMaxDynamicSharedMemorySize, GSM_TOTAL);
    cudaFuncSetAttribute(gemm_hmma<false>, cudaFuncAttributeMaxDynamicSharedMemorySize, GSM_TOTAL);
    cudaFuncSetAttribute(attn_hmma, cudaFuncAttributeMaxDynamicSharedMemorySize, ATT_SMEM);

    // 0) convert operands to fp16
    round16_kernel<<<2048, 256>>>(Wqkv, wq_h, QKV_N * HID);
    round16_kernel<<<2048, 256>>>(Wd, wd_h, HID * HID);
    round16_kernel<<<1024, 256>>>(hs, a_h, SEQ * HID);

    // 1) fused QKV projection -> fp16 qkv
    {
        dim3 grid(QKV_N / 128, SEQ / 128);
        gemm_hmma<true><<<grid, 256, GSM_TOTAL>>>(a_h, wq_h, bqkv, nullptr,
                                                  qkv_h, SEQ, QKV_N, HID);
    }
    // 2) tensor-core flash attention -> ctx fp16
    {
        dim3 grid(SEQ / 64, NHEAD);
        attn_hmma<<<grid, 128, ATT_SMEM>>>(qkv_h, alibi, a_h);
    }
    // 3) dense projection + bias + residual -> fp32 out
    {
        dim3 grid(HID / 128, SEQ / 128);
        gemm_hmma<false><<<grid, 256, GSM_TOTAL>>>(a_h, wd_h, bd, residual,
                                                   out, SEQ, HID, HID);
    }
}